// round 1
// baseline (speedup 1.0000x reference)
#include <cuda_runtime.h>

#define NN 50000
#define EE 800000
#define ET (EE + NN)   // edges + self loops

// ---------------- scratch (static __device__ globals; no allocs) -------------
__device__ int   g_rowptr[NN + 1];
__device__ int   g_cursor[NN];
__device__ int   g_csr[ET];
__device__ float g_hin[NN * 32];     // current layer input features (din<=32)
__device__ float g_h[NN * 192];      // h = x @ W^T  [N, H*dout]
__device__ float g_als[NN * 8];      // per-node alpha_src logits, padded stride 8
__device__ float g_ald[NN * 8];      // per-node alpha_dst logits
__device__ float g_wt[6144];         // transposed weights [din, H*dout]

__device__ __forceinline__ float selu_f(float x) {
    const float sc = 1.0507009873554805f;
    const float al = 1.6732632423543772f;
    return x > 0.f ? sc * x : sc * al * (__expf(x) - 1.f);
}
__device__ __forceinline__ float lrelu(float x) {
    return x > 0.f ? x : 0.2f * x;
}

// ---------------- CSR construction ------------------------------------------
__global__ void k_init_cursor() {
    int i = blockIdx.x * blockDim.x + threadIdx.x;
    if (i < NN) g_cursor[i] = 1;     // self-loop pre-counted
}

__global__ void k_count(const int* __restrict__ dst) {
    int i = blockIdx.x * blockDim.x + threadIdx.x;
    if (i < EE) atomicAdd(&g_cursor[dst[i]], 1);
}

// single-block exclusive scan of g_cursor[0..NN) -> g_rowptr[0..NN]
__global__ void k_scan() {
    __shared__ int s_wtot[33];
    __shared__ int s_carry;
    int tid = threadIdx.x, lane = tid & 31, wid = tid >> 5;
    if (tid == 0) s_carry = 0;
    __syncthreads();
    for (int base = 0; base < NN; base += 1024) {
        int i = base + tid;
        int v = (i < NN) ? g_cursor[i] : 0;
        int x = v;
        #pragma unroll
        for (int o = 1; o < 32; o <<= 1) {
            int t = __shfl_up_sync(0xffffffffu, x, o);
            if (lane >= o) x += t;
        }
        if (lane == 31) s_wtot[wid] = x;
        __syncthreads();
        if (wid == 0) {
            int w = s_wtot[lane];
            int y = w;
            #pragma unroll
            for (int o = 1; o < 32; o <<= 1) {
                int t = __shfl_up_sync(0xffffffffu, y, o);
                if (lane >= o) y += t;
            }
            s_wtot[lane] = y - w;               // exclusive prefix of warp totals
            if (lane == 31) s_wtot[32] = y;     // block total
        }
        __syncthreads();
        int excl = s_carry + s_wtot[wid] + (x - v);
        if (i < NN) g_rowptr[i] = excl;
        int btot = s_wtot[32];
        __syncthreads();
        if (tid == 0) s_carry += btot;
        __syncthreads();
    }
    if (tid == 0) g_rowptr[NN] = s_carry;
}

__global__ void k_copy_cursor() {
    int i = blockIdx.x * blockDim.x + threadIdx.x;
    if (i < NN) g_cursor[i] = g_rowptr[i];
}

__global__ void k_scatter(const int* __restrict__ src, const int* __restrict__ dst) {
    int i = blockIdx.x * blockDim.x + threadIdx.x;
    if (i >= ET) return;
    int s, d;
    if (i < EE) { s = src[i]; d = dst[i]; }
    else        { s = d = i - EE; }      // self loop
    int pos = atomicAdd(&g_cursor[d], 1);
    g_csr[pos] = s;
}

// ---------------- initial linear + SELU -------------------------------------
__global__ void k_lin0(const float* __restrict__ x, const float* __restrict__ w,
                       const float* __restrict__ b) {
    int idx = blockIdx.x * blockDim.x + threadIdx.x;
    if (idx >= NN * 16) return;
    int n = idx >> 4, c = idx & 15;
    const float* xr = x + n * 10;
    const float* wr = w + c * 10;
    float acc = b[c];
    #pragma unroll
    for (int d = 0; d < 10; d++) acc += xr[d] * wr[d];
    g_hin[idx] = selu_f(acc);
}

// ---------------- per-layer kernels -----------------------------------------
__global__ void k_transpose(const float* __restrict__ W, int din, int hd) {
    int i = blockIdx.x * blockDim.x + threadIdx.x;
    if (i >= din * hd) return;
    int d = i / hd, k = i - d * hd;
    g_wt[d * hd + k] = W[k * din + d];
}

template <int DIN, int HD>
__global__ void k_transform() {
    int idx = blockIdx.x * blockDim.x + threadIdx.x;
    if (idx >= NN * HD) return;
    int n = idx / HD, k = idx - n * HD;
    const float* xr = g_hin + n * DIN;
    float acc = 0.f;
    #pragma unroll
    for (int d = 0; d < DIN; d++) acc += xr[d] * g_wt[d * HD + k];
    g_h[idx] = acc;
}

template <int DOUT>
__global__ void k_alpha(const float* __restrict__ asrc, const float* __restrict__ adst) {
    int idx = blockIdx.x * blockDim.x + threadIdx.x;
    if (idx >= NN * 6) return;
    int n = idx / 6, h = idx - n * 6;
    const float* hr = g_h + n * (6 * DOUT) + h * DOUT;
    const float* as = asrc + h * DOUT;
    const float* ad = adst + h * DOUT;
    float sa = 0.f, sd = 0.f;
    #pragma unroll
    for (int o = 0; o < DOUT; o++) { sa += hr[o] * as[o]; sd += hr[o] * ad[o]; }
    g_als[n * 8 + h] = sa;
    g_ald[n * 8 + h] = sd;
}

// warp-per-dst-node: softmax over incoming edges + weighted aggregation +
// head mean + bias + SELU, all fused. Writes out[n*DOUT + o].
template <int DOUT>
__global__ void k_gat(const float* __restrict__ bias, float* __restrict__ out) {
    constexpr int HD = 6 * DOUT;
    constexpr int R  = (HD + 31) / 32;
    int wg = (blockIdx.x * blockDim.x + threadIdx.x) >> 5;
    int lane = threadIdx.x & 31;
    if (wg >= NN) return;
    int n = wg;
    int start = g_rowptr[n], end = g_rowptr[n + 1];

    // broadcast alpha_dst logits of node n to all lanes
    float ald_l = (lane < 6) ? g_ald[n * 8 + lane] : 0.f;
    float adh[6];
    #pragma unroll
    for (int h = 0; h < 6; h++) adh[h] = __shfl_sync(0xffffffffu, ald_l, h);

    // ---- pass 1: per-head max over edges (lanes parallel over edges) ----
    float m[6];
    #pragma unroll
    for (int h = 0; h < 6; h++) m[h] = -1e30f;
    for (int j = start + lane; j < end; j += 32) {
        int s = g_csr[j];
        const float* ap = g_als + s * 8;
        #pragma unroll
        for (int h = 0; h < 6; h++) {
            float e = lrelu(ap[h] + adh[h]);
            m[h] = fmaxf(m[h], e);
        }
    }
    #pragma unroll
    for (int h = 0; h < 6; h++)
        #pragma unroll
        for (int o = 16; o > 0; o >>= 1)
            m[h] = fmaxf(m[h], __shfl_xor_sync(0xffffffffu, m[h], o));

    // ---- pass 2: per-head sum of exp(e - m) ----
    float sm[6];
    #pragma unroll
    for (int h = 0; h < 6; h++) sm[h] = 0.f;
    for (int j = start + lane; j < end; j += 32) {
        int s = g_csr[j];
        const float* ap = g_als + s * 8;
        #pragma unroll
        for (int h = 0; h < 6; h++) {
            float e = lrelu(ap[h] + adh[h]);
            sm[h] += __expf(e - m[h]);
        }
    }
    #pragma unroll
    for (int h = 0; h < 6; h++)
        #pragma unroll
        for (int o = 16; o > 0; o >>= 1)
            sm[h] += __shfl_xor_sync(0xffffffffu, sm[h], o);

    // lane h (<6) keeps its head's (m, 1/s, ald)
    float m_sel = 0.f, is_sel = 0.f;
    #pragma unroll
    for (int h = 0; h < 6; h++)
        if (lane == h) { m_sel = m[h]; is_sel = 1.f / sm[h]; }
    float ad_sel = ald_l;

    // which head each (lane, r) accumulator belongs to (loop invariant)
    int hsel[R];
    #pragma unroll
    for (int r = 0; r < R; r++) hsel[r] = (lane + r * 32) / DOUT;

    // ---- pass 3: sequential over edges; lanes parallel over output dims ----
    float acc[R];
    #pragma unroll
    for (int r = 0; r < R; r++) acc[r] = 0.f;
    for (int j = start; j < end; j++) {
        int s = g_csr[j];                      // uniform across warp
        float a = 0.f;
        if (lane < 6) {
            float e = lrelu(g_als[s * 8 + lane] + ad_sel);
            a = __expf(e - m_sel) * is_sel;    // alpha for head=lane
        }
        const float* hp = g_h + (size_t)s * HD;
        #pragma unroll
        for (int r = 0; r < R; r++) {
            float av = __shfl_sync(0xffffffffu, a, hsel[r]);
            int idx = lane + r * 32;
            if (idx < HD) acc[r] += hp[idx] * av;
        }
    }

    // ---- head mean + bias + SELU ----
    if (DOUT == 32) {
        float mean = (acc[0] + acc[1] + acc[2] + acc[3] + acc[4] + acc[5]) * (1.f / 6.f);
        out[n * 32 + lane] = selu_f(mean + bias[lane]);
    } else if (DOUT == 16) {
        float partial = acc[0] + acc[1] + acc[2];
        float total = partial + __shfl_xor_sync(0xffffffffu, partial, 16);
        if (lane < 16) out[n * 16 + lane] = selu_f(total * (1.f / 6.f) + bias[lane]);
    } else { // DOUT == 2
        float v = (lane < 12) ? acc[0] : 0.f;
        v += __shfl_xor_sync(0xffffffffu, v, 2);
        v += __shfl_xor_sync(0xffffffffu, v, 4);
        v += __shfl_xor_sync(0xffffffffu, v, 8);
        if (lane < 2) out[n * 2 + lane] = selu_f(v * (1.f / 6.f) + bias[lane]);
    }
}

// ---------------- host launcher ---------------------------------------------
static inline int cdiv(int a, int b) { return (a + b - 1) / b; }

extern "C" void kernel_launch(void* const* d_in, const int* in_sizes, int n_in,
                              void* d_out, int out_size) {
    (void)in_sizes; (void)n_in; (void)out_size;
    const float* x     = (const float*)d_in[0];
    const int*   ei    = (const int*)d_in[1];
    const float* lin_w = (const float*)d_in[2];
    const float* lin_b = (const float*)d_in[3];
    const float* W[4]  = { (const float*)d_in[4],  (const float*)d_in[8],
                           (const float*)d_in[12], (const float*)d_in[16] };
    const float* AS[4] = { (const float*)d_in[5],  (const float*)d_in[9],
                           (const float*)d_in[13], (const float*)d_in[17] };
    const float* AD[4] = { (const float*)d_in[6],  (const float*)d_in[10],
                           (const float*)d_in[14], (const float*)d_in[18] };
    const float* B[4]  = { (const float*)d_in[7],  (const float*)d_in[11],
                           (const float*)d_in[15], (const float*)d_in[19] };
    float* out = (float*)d_out;

    float* g_hin_ptr = nullptr;
    cudaGetSymbolAddress((void**)&g_hin_ptr, g_hin);

    // CSR by dst (rebuilt every call; deterministic work)
    k_init_cursor<<<cdiv(NN, 256), 256>>>();
    k_count<<<cdiv(EE, 256), 256>>>(ei + EE);
    k_scan<<<1, 1024>>>();
    k_copy_cursor<<<cdiv(NN, 256), 256>>>();
    k_scatter<<<cdiv(ET, 256), 256>>>(ei, ei + EE);

    // initial linear + SELU -> g_hin [N,16]
    k_lin0<<<cdiv(NN * 16, 256), 256>>>(x, lin_w, lin_b);

    const int din_l[4]  = {16, 32, 32, 16};
    const int dout_l[4] = {32, 32, 16, 2};

    for (int l = 0; l < 4; l++) {
        int din = din_l[l], dout = dout_l[l], hd = 6 * dout;
        k_transpose<<<cdiv(din * hd, 256), 256>>>(W[l], din, hd);
        if (l == 0)      k_transform<16, 192><<<cdiv(NN * 192, 256), 256>>>();
        else if (l == 1) k_transform<32, 192><<<cdiv(NN * 192, 256), 256>>>();
        else if (l == 2) k_transform<32,  96><<<cdiv(NN *  96, 256), 256>>>();
        else             k_transform<16,  12><<<cdiv(NN *  12, 256), 256>>>();

        if (dout == 32)      k_alpha<32><<<cdiv(NN * 6, 256), 256>>>(AS[l], AD[l]);
        else if (dout == 16) k_alpha<16><<<cdiv(NN * 6, 256), 256>>>(AS[l], AD[l]);
        else                 k_alpha<2><<<cdiv(NN * 6, 256), 256>>>(AS[l], AD[l]);

        float* layer_out = (l == 3) ? out : g_hin_ptr;
        // 8 warps per block, one warp per node
        int blocks = cdiv(NN, 8);
        if (dout == 32)      k_gat<32><<<blocks, 256>>>(B[l], layer_out);
        else if (dout == 16) k_gat<16><<<blocks, 256>>>(B[l], layer_out);
        else                 k_gat<2><<<blocks, 256>>>(B[l], layer_out);
    }
}

// round 2
// speedup vs baseline: 1.0636x; 1.0636x over previous
#include <cuda_runtime.h>

#define NN 50000
#define EE 800000
#define ET (EE + NN)   // edges + self loops
#define FULLM 0xffffffffu

// ---------------- scratch (static __device__ globals; no allocs) -------------
__device__ int    g_rowptr[NN + 1];
__device__ int    g_cursor[NN];
__device__ int    g_csr[ET];
__device__ float4 g_hin4[NN * 8];    // node features [n][din], din<=32 (float4 rows)
__device__ float4 g_h4[NN * 48];     // transformed  [n][HD],  HD<=192
__device__ float4 g_ae4[NN * 4];     // [n][16]: +0..5 src logits, +8..13 dst logits

__device__ __forceinline__ float selu_f(float x) {
    const float sc = 1.0507009873554805f;
    const float al = 1.6732632423543772f;
    return x > 0.f ? sc * x : sc * al * (__expf(x) - 1.f);
}
__device__ __forceinline__ float lrelu(float x) { return x > 0.f ? x : 0.2f * x; }
__device__ __forceinline__ float f4c(const float4& v, int j) {
    return j == 0 ? v.x : j == 1 ? v.y : j == 2 ? v.z : v.w;
}
__device__ __forceinline__ void fma4(float4& a, const float4& v, float s) {
    a.x += v.x * s; a.y += v.y * s; a.z += v.z * s; a.w += v.w * s;
}

// ---------------- CSR construction ------------------------------------------
__global__ void k_init_cursor() {
    int i = blockIdx.x * blockDim.x + threadIdx.x;
    if (i < NN) g_cursor[i] = 1;     // self-loop pre-counted
}

__global__ void k_count(const int* __restrict__ dst) {
    int i = blockIdx.x * blockDim.x + threadIdx.x;
    if (i < EE) atomicAdd(&g_cursor[dst[i]], 1);
}

// single-block exclusive scan; writes rowptr AND resets cursor to row start
__global__ void k_scan() {
    __shared__ int s_wtot[33];
    __shared__ int s_carry;
    int tid = threadIdx.x, lane = tid & 31, wid = tid >> 5;
    if (tid == 0) s_carry = 0;
    __syncthreads();
    for (int base = 0; base < NN; base += 1024) {
        int i = base + tid;
        int v = (i < NN) ? g_cursor[i] : 0;
        int x = v;
        #pragma unroll
        for (int o = 1; o < 32; o <<= 1) {
            int t = __shfl_up_sync(FULLM, x, o);
            if (lane >= o) x += t;
        }
        if (lane == 31) s_wtot[wid] = x;
        __syncthreads();
        if (wid == 0) {
            int w = s_wtot[lane];
            int y = w;
            #pragma unroll
            for (int o = 1; o < 32; o <<= 1) {
                int t = __shfl_up_sync(FULLM, y, o);
                if (lane >= o) y += t;
            }
            s_wtot[lane] = y - w;
            if (lane == 31) s_wtot[32] = y;
        }
        __syncthreads();
        int excl = s_carry + s_wtot[wid] + (x - v);
        if (i < NN) { g_rowptr[i] = excl; g_cursor[i] = excl; }
        int btot = s_wtot[32];
        __syncthreads();
        if (tid == 0) s_carry += btot;
        __syncthreads();
    }
    if (tid == 0) g_rowptr[NN] = s_carry;
}

// scatter edges into CSR + initial linear+SELU, fused (independent block ranges)
#define SCAT_BLOCKS ((ET + 255) / 256)
#define LIN0_BLOCKS ((NN * 16 + 255) / 256)
__global__ void k_scatter_lin0(const int* __restrict__ ei, const float* __restrict__ x,
                               const float* __restrict__ lw, const float* __restrict__ lb) {
    if (blockIdx.x < SCAT_BLOCKS) {
        int i = blockIdx.x * 256 + threadIdx.x;
        if (i >= ET) return;
        int s, d;
        if (i < EE) { s = ei[i]; d = ei[EE + i]; }
        else        { s = d = i - EE; }
        int pos = atomicAdd(&g_cursor[d], 1);
        g_csr[pos] = s;
    } else {
        int i = (blockIdx.x - SCAT_BLOCKS) * 256 + threadIdx.x;
        if (i >= NN * 16) return;
        int n = i >> 4, c = i & 15;
        const float* xr = x + n * 10;
        const float* wr = lw + c * 10;
        float acc = lb[c];
        #pragma unroll
        for (int d = 0; d < 10; d++) acc += xr[d] * wr[d];
        reinterpret_cast<float*>(g_hin4)[i] = selu_f(acc);
    }
}

// ---------------- per-layer: transform + alpha logits, fused ----------------
// Block range [0, NB_T): h = x @ W^T, 4 nodes x float4-column tile per thread,
//                        W^T staged in smem.
// Block range [NB_T, ..): alpha logits als/ald = x @ (W_h^T a_h); the tiny
//                        folded matrix wa[din][12] computed per block in smem.
template <int DIN, int DOUT>
__global__ __launch_bounds__(256) void k_feat(const float* __restrict__ W,
                                              const float* __restrict__ asv,
                                              const float* __restrict__ adv) {
    constexpr int HD = 6 * DOUT;
    constexpr int C4 = HD / 4;
    constexpr int NB_T = ((NN / 4) * C4 + 255) / 256;
    __shared__ float s_buf[DIN * HD];

    if (blockIdx.x < NB_T) {
        // stage W transposed: s_buf[d*HD + k] = W[k*DIN + d]
        for (int i = threadIdx.x; i < DIN * HD; i += 256) {
            int k = i / DIN, d = i - k * DIN;
            s_buf[d * HD + k] = W[i];
        }
        __syncthreads();
        int t = blockIdx.x * 256 + threadIdx.x;
        if (t >= (NN / 4) * C4) return;
        int c4 = t % C4, nb = t / C4;
        int n0 = nb * 4;
        const float4* x4 = g_hin4;
        const float4* w4 = reinterpret_cast<const float4*>(s_buf);  // [DIN][C4]
        float4 acc0 = {0,0,0,0}, acc1 = {0,0,0,0}, acc2 = {0,0,0,0}, acc3 = {0,0,0,0};
        #pragma unroll
        for (int dc = 0; dc < DIN / 4; dc++) {
            float4 xv0 = x4[(n0 + 0) * (DIN / 4) + dc];
            float4 xv1 = x4[(n0 + 1) * (DIN / 4) + dc];
            float4 xv2 = x4[(n0 + 2) * (DIN / 4) + dc];
            float4 xv3 = x4[(n0 + 3) * (DIN / 4) + dc];
            #pragma unroll
            for (int j = 0; j < 4; j++) {
                float4 wv = w4[(dc * 4 + j) * C4 + c4];
                fma4(acc0, wv, f4c(xv0, j));
                fma4(acc1, wv, f4c(xv1, j));
                fma4(acc2, wv, f4c(xv2, j));
                fma4(acc3, wv, f4c(xv3, j));
            }
        }
        g_h4[(n0 + 0) * C4 + c4] = acc0;
        g_h4[(n0 + 1) * C4 + c4] = acc1;
        g_h4[(n0 + 2) * C4 + c4] = acc2;
        g_h4[(n0 + 3) * C4 + c4] = acc3;
    } else {
        // fold attention vectors: wa[d][hh] (hh<6: src, hh>=6: dst)
        for (int i = threadIdx.x; i < 12 * DIN; i += 256) {
            int d = i / 12, hh = i - d * 12;
            int head = hh % 6;
            const float* av = (hh < 6 ? asv : adv) + head * DOUT;
            float s = 0.f;
            #pragma unroll
            for (int o = 0; o < DOUT; o++) s += av[o] * W[(head * DOUT + o) * DIN + d];
            s_buf[d * 12 + hh] = s;
        }
        __syncthreads();
        int t2 = (blockIdx.x - NB_T) * 256 + threadIdx.x;
        if (t2 >= NN * 12) return;
        int n = t2 / 12, hh = t2 - n * 12;
        const float* xr = reinterpret_cast<const float*>(g_hin4) + n * DIN;
        float acc = 0.f;
        #pragma unroll
        for (int d = 0; d < DIN; d++) acc += xr[d] * s_buf[d * 12 + hh];
        reinterpret_cast<float*>(g_ae4)[n * 16 + (hh < 6 ? hh : hh + 2)] = acc;
    }
}

// ---------------- fused GAT: online softmax + aggregation + mean/bias/SELU --
template <int DOUT>
__global__ __launch_bounds__(256) void k_gat(const float* __restrict__ bias,
                                             float* __restrict__ out) {
    constexpr int HD = 6 * DOUT;
    constexpr int SRED = (DOUT > 2) ? 8 * HD : 8;
    __shared__ float s_red[SRED];
    int w = threadIdx.x >> 5, lane = threadIdx.x & 31;
    int n = blockIdx.x * 8 + w;
    if (n >= NN) return;
    int start = g_rowptr[n], end = g_rowptr[n + 1];

    const float4* ae4 = g_ae4;
    const float*  aef = reinterpret_cast<const float*>(g_ae4);
    float4 d03 = ae4[n * 4 + 2];
    float4 d45 = ae4[n * 4 + 3];
    float adh[6] = {d03.x, d03.y, d03.z, d03.w, d45.x, d45.y};

    // ---- online softmax over incoming edges (lanes strided over edges) ----
    float m[6], sm[6];
    #pragma unroll
    for (int h = 0; h < 6; h++) { m[h] = -1e30f; sm[h] = 0.f; }
    for (int j = start + lane; j < end; j += 32) {
        int s = g_csr[j];
        float4 a03 = ae4[s * 4 + 0];
        float4 a45 = ae4[s * 4 + 1];
        float ev[6] = {a03.x + adh[0], a03.y + adh[1], a03.z + adh[2],
                       a03.w + adh[3], a45.x + adh[4], a45.y + adh[5]};
        #pragma unroll
        for (int h = 0; h < 6; h++) {
            float e  = lrelu(ev[h]);
            float mn = fmaxf(m[h], e);
            sm[h] = sm[h] * __expf(m[h] - mn) + __expf(e - mn);
            m[h] = mn;
        }
    }
    #pragma unroll
    for (int h = 0; h < 6; h++) {
        #pragma unroll
        for (int o = 16; o > 0; o >>= 1) {
            float mo = __shfl_xor_sync(FULLM, m[h], o);
            float so = __shfl_xor_sync(FULLM, sm[h], o);
            float mn = fmaxf(m[h], mo);
            sm[h] = sm[h] * __expf(m[h] - mn) + so * __expf(mo - mn);
            m[h] = mn;
        }
    }
    float inv[6];
    #pragma unroll
    for (int h = 0; h < 6; h++) inv[h] = 1.f / sm[h];

    const float4* gh4 = g_h4;
    const float*  ghf = reinterpret_cast<const float*>(g_h4);
    float* sr = s_red + ((DOUT > 2) ? w * HD : 0);

    if constexpr (DOUT == 2) {
        // edge-per-lane: 12 accumulators, full alpha computed per lane
        float acc[12];
        #pragma unroll
        for (int k = 0; k < 12; k++) acc[k] = 0.f;
        for (int j = start + lane; j < end; j += 32) {
            int s = g_csr[j];
            float4 a03 = ae4[s * 4 + 0];
            float4 a45 = ae4[s * 4 + 1];
            float ev[6] = {a03.x + adh[0], a03.y + adh[1], a03.z + adh[2],
                           a03.w + adh[3], a45.x + adh[4], a45.y + adh[5]};
            float al[6];
            #pragma unroll
            for (int h = 0; h < 6; h++)
                al[h] = __expf(lrelu(ev[h]) - m[h]) * inv[h];
            const float4* hp = reinterpret_cast<const float4*>(ghf + s * 12);
            float4 v0 = hp[0], v1 = hp[1], v2 = hp[2];
            acc[0] += v0.x * al[0]; acc[1]  += v0.y * al[0];
            acc[2] += v0.z * al[1]; acc[3]  += v0.w * al[1];
            acc[4] += v1.x * al[2]; acc[5]  += v1.y * al[2];
            acc[6] += v1.z * al[3]; acc[7]  += v1.w * al[3];
            acc[8] += v2.x * al[4]; acc[9]  += v2.y * al[4];
            acc[10]+= v2.z * al[5]; acc[11] += v2.w * al[5];
        }
        #pragma unroll
        for (int k = 0; k < 12; k++)
            #pragma unroll
            for (int o = 16; o > 0; o >>= 1)
                acc[k] += __shfl_xor_sync(FULLM, acc[k], o);
        if (lane < 2) {
            float s6 = acc[lane] + acc[2 + lane] + acc[4 + lane] +
                       acc[6 + lane] + acc[8 + lane] + acc[10 + lane];
            out[n * 2 + lane] = selu_f(s6 * (1.f / 6.f) + bias[lane]);
        }
        return;
    }

    // per-lane head params for alpha computation (lanes 0..5 own head=lane)
    float m_sel = 0.f, inv_sel = 0.f, ad_sel = 0.f;
    #pragma unroll
    for (int h = 0; h < 6; h++)
        if (lane == h) { m_sel = m[h]; inv_sel = inv[h]; ad_sel = adh[h]; }

    if constexpr (DOUT == 32) {
        // lane owns dims [lane*4, +4) (head lane>>3) and, for lane<16,
        // dims [128+lane*4, +4) (head 4+(lane>>3))
        int src0 = lane >> 3;
        int src1 = 4 + (lane >> 3);
        float4 acc0 = {0,0,0,0}, acc1 = {0,0,0,0};
        int j = start;
        for (; j + 2 <= end; j += 2) {
            int s0 = g_csr[j], s1 = g_csr[j + 1];
            float a0 = 0.f, a1 = 0.f;
            if (lane < 6) {
                float e0 = lrelu(aef[s0 * 16 + lane] + ad_sel);
                float e1 = lrelu(aef[s1 * 16 + lane] + ad_sel);
                a0 = __expf(e0 - m_sel) * inv_sel;
                a1 = __expf(e1 - m_sel) * inv_sel;
            }
            const float4* h0 = gh4 + s0 * 48;
            const float4* h1 = gh4 + s1 * 48;
            float4 p0 = h0[lane], p1 = h1[lane];
            float4 q0 = {0,0,0,0}, q1 = {0,0,0,0};
            if (lane < 16) { q0 = h0[32 + lane]; q1 = h1[32 + lane]; }
            float av0 = __shfl_sync(FULLM, a0, src0);
            float aw0 = __shfl_sync(FULLM, a0, src1);
            float av1 = __shfl_sync(FULLM, a1, src0);
            float aw1 = __shfl_sync(FULLM, a1, src1);
            fma4(acc0, p0, av0); fma4(acc0, p1, av1);
            fma4(acc1, q0, aw0); fma4(acc1, q1, aw1);
        }
        if (j < end) {
            int s0 = g_csr[j];
            float a0 = 0.f;
            if (lane < 6) {
                float e0 = lrelu(aef[s0 * 16 + lane] + ad_sel);
                a0 = __expf(e0 - m_sel) * inv_sel;
            }
            const float4* h0 = gh4 + s0 * 48;
            float4 p0 = h0[lane];
            float4 q0 = {0,0,0,0};
            if (lane < 16) q0 = h0[32 + lane];
            float av0 = __shfl_sync(FULLM, a0, src0);
            float aw0 = __shfl_sync(FULLM, a0, src1);
            fma4(acc0, p0, av0);
            fma4(acc1, q0, aw0);
        }
        sr[lane * 4 + 0] = acc0.x; sr[lane * 4 + 1] = acc0.y;
        sr[lane * 4 + 2] = acc0.z; sr[lane * 4 + 3] = acc0.w;
        if (lane < 16) {
            sr[128 + lane * 4 + 0] = acc1.x; sr[128 + lane * 4 + 1] = acc1.y;
            sr[128 + lane * 4 + 2] = acc1.z; sr[128 + lane * 4 + 3] = acc1.w;
        }
        __syncwarp();
        float o0 = sr[lane] + sr[32 + lane] + sr[64 + lane] +
                   sr[96 + lane] + sr[128 + lane] + sr[160 + lane];
        out[n * 32 + lane] = selu_f(o0 * (1.f / 6.f) + bias[lane]);
    } else { // DOUT == 16, HD = 96
        int srch = lane >> 2;  // head for lane<24; >=6 for lane>=24 (alpha=0)
        float4 acc0 = {0,0,0,0};
        int j = start;
        for (; j + 2 <= end; j += 2) {
            int s0 = g_csr[j], s1 = g_csr[j + 1];
            float a0 = 0.f, a1 = 0.f;
            if (lane < 6) {
                float e0 = lrelu(aef[s0 * 16 + lane] + ad_sel);
                float e1 = lrelu(aef[s1 * 16 + lane] + ad_sel);
                a0 = __expf(e0 - m_sel) * inv_sel;
                a1 = __expf(e1 - m_sel) * inv_sel;
            }
            const float4* h0 = gh4 + s0 * 24;
            const float4* h1 = gh4 + s1 * 24;
            float4 p0 = {0,0,0,0}, p1 = {0,0,0,0};
            if (lane < 24) { p0 = h0[lane]; p1 = h1[lane]; }
            float av0 = __shfl_sync(FULLM, a0, srch & 7);
            float av1 = __shfl_sync(FULLM, a1, srch & 7);
            fma4(acc0, p0, av0); fma4(acc0, p1, av1);
        }
        if (j < end) {
            int s0 = g_csr[j];
            float a0 = 0.f;
            if (lane < 6) {
                float e0 = lrelu(aef[s0 * 16 + lane] + ad_sel);
                a0 = __expf(e0 - m_sel) * inv_sel;
            }
            const float4* h0 = gh4 + s0 * 24;
            float4 p0 = {0,0,0,0};
            if (lane < 24) p0 = h0[lane];
            float av0 = __shfl_sync(FULLM, a0, srch & 7);
            fma4(acc0, p0, av0);
        }
        if (lane < 24) {
            sr[lane * 4 + 0] = acc0.x; sr[lane * 4 + 1] = acc0.y;
            sr[lane * 4 + 2] = acc0.z; sr[lane * 4 + 3] = acc0.w;
        }
        __syncwarp();
        if (lane < 16) {
            float o0 = sr[lane] + sr[16 + lane] + sr[32 + lane] +
                       sr[48 + lane] + sr[64 + lane] + sr[80 + lane];
            out[n * 16 + lane] = selu_f(o0 * (1.f / 6.f) + bias[lane]);
        }
    }
}

// ---------------- host launcher ---------------------------------------------
static inline int cdiv(int a, int b) { return (a + b - 1) / b; }

extern "C" void kernel_launch(void* const* d_in, const int* in_sizes, int n_in,
                              void* d_out, int out_size) {
    (void)in_sizes; (void)n_in; (void)out_size;
    const float* x     = (const float*)d_in[0];
    const int*   ei    = (const int*)d_in[1];
    const float* lin_w = (const float*)d_in[2];
    const float* lin_b = (const float*)d_in[3];
    const float* W[4]  = { (const float*)d_in[4],  (const float*)d_in[8],
                           (const float*)d_in[12], (const float*)d_in[16] };
    const float* AS[4] = { (const float*)d_in[5],  (const float*)d_in[9],
                           (const float*)d_in[13], (const float*)d_in[17] };
    const float* AD[4] = { (const float*)d_in[6],  (const float*)d_in[10],
                           (const float*)d_in[14], (const float*)d_in[18] };
    const float* B[4]  = { (const float*)d_in[7],  (const float*)d_in[11],
                           (const float*)d_in[15], (const float*)d_in[19] };
    float* out = (float*)d_out;

    float* g_hin_ptr = nullptr;
    cudaGetSymbolAddress((void**)&g_hin_ptr, g_hin4);

    // launch 0-3: CSR build (+ lin0 fused into scatter)
    k_init_cursor<<<cdiv(NN, 256), 256>>>();
    k_count<<<cdiv(EE, 256), 256>>>(ei + EE);
    k_scan<<<1, 1024>>>();
    k_scatter_lin0<<<SCAT_BLOCKS + LIN0_BLOCKS, 256>>>(ei, x, lin_w, lin_b);

    const int gat_blocks = cdiv(NN, 8);
    const int nba = cdiv(NN * 12, 256);

    // layer 1: DIN=16, DOUT=32        (launch 4: feat, launch 5: gat <- ncu -s 5)
    {
        const int nbt = cdiv((NN / 4) * 48, 256);
        k_feat<16, 32><<<nbt + nba, 256>>>(W[0], AS[0], AD[0]);
        k_gat<32><<<gat_blocks, 256>>>(B[0], g_hin_ptr);
    }
    // layer 2: DIN=32, DOUT=32
    {
        const int nbt = cdiv((NN / 4) * 48, 256);
        k_feat<32, 32><<<nbt + nba, 256>>>(W[1], AS[1], AD[1]);
        k_gat<32><<<gat_blocks, 256>>>(B[1], g_hin_ptr);
    }
    // layer 3: DIN=32, DOUT=16
    {
        const int nbt = cdiv((NN / 4) * 24, 256);
        k_feat<32, 16><<<nbt + nba, 256>>>(W[2], AS[2], AD[2]);
        k_gat<16><<<gat_blocks, 256>>>(B[2], g_hin_ptr);
    }
    // layer 4: DIN=16, DOUT=2
    {
        const int nbt = cdiv((NN / 4) * 3, 256);
        k_feat<16, 2><<<nbt + nba, 256>>>(W[3], AS[3], AD[3]);
        k_gat<2><<<gat_blocks, 256>>>(B[3], out);
    }
}

// round 4
// speedup vs baseline: 1.2650x; 1.1894x over previous
#include <cuda_runtime.h>

#define NN 50000
#define EE 800000
#define ET (EE + NN)   // edges + self loops
#define FULLM 0xffffffffu

__host__ __device__ constexpr int CDIV(int a, int b) { return (a + b - 1) / b; }

// ---------------- scratch (static __device__ globals; no allocs) -------------
__device__ int    g_rowptr[NN + 1];
__device__ int    g_cursor[NN];          // zero at call start (invariant)
__device__ int    g_csr[ET];
__device__ float4 g_hin4[NN * 8];        // node features [n][din], din<=32
__device__ float4 g_h4[NN * 48];         // transformed  [n][HD],  HD<=192
__device__ float4 g_ae4[NN * 4];         // [n][16]: 0..5 src logits, 8..13 dst logits

__device__ __forceinline__ float selu_f(float x) {
    const float sc = 1.0507009873554805f;
    const float al = 1.6732632423543772f;
    return x > 0.f ? sc * x : sc * al * (__expf(x) - 1.f);
}
__device__ __forceinline__ float lrelu(float x) { return x > 0.f ? x : 0.2f * x; }
__device__ __forceinline__ float f4c(const float4& v, int j) {
    return j == 0 ? v.x : j == 1 ? v.y : j == 2 ? v.z : v.w;
}
__device__ __forceinline__ void fma4(float4& a, const float4& v, float s) {
    a.x += v.x * s; a.y += v.y * s; a.z += v.z * s; a.w += v.w * s;
}

// ---------------- launch 0: degree count + initial linear -------------------
#define CNT_BLOCKS  CDIV(EE, 256)
#define LIN0_BLOCKS CDIV(NN * 16, 256)
__global__ __launch_bounds__(256) void k_count_lin0(const int* __restrict__ ei,
                                                    const float* __restrict__ x,
                                                    const float* __restrict__ lw,
                                                    const float* __restrict__ lb) {
    if (blockIdx.x < CNT_BLOCKS) {
        int i = blockIdx.x * 256 + threadIdx.x;
        if (i < EE) atomicAdd(&g_cursor[ei[EE + i]], 1);
    } else {
        int i = (blockIdx.x - CNT_BLOCKS) * 256 + threadIdx.x;
        if (i >= NN * 16) return;
        int n = i >> 4, c = i & 15;
        const float* xr = x + n * 10;
        const float* wr = lw + c * 10;
        float acc = lb[c];
        #pragma unroll
        for (int d = 0; d < 10; d++) acc += xr[d] * wr[d];
        reinterpret_cast<float*>(g_hin4)[i] = selu_f(acc);
    }
}

// ---------------- launch 1: scan (adds self-loop +1, resets cursor) ---------
__global__ void k_scan() {
    __shared__ int s_wtot[33];
    __shared__ int s_carry;
    int tid = threadIdx.x, lane = tid & 31, wid = tid >> 5;
    if (tid == 0) s_carry = 0;
    __syncthreads();
    for (int base = 0; base < NN; base += 1024) {
        int i = base + tid;
        int v = (i < NN) ? (g_cursor[i] + 1) : 0;   // +1 self loop
        int x = v;
        #pragma unroll
        for (int o = 1; o < 32; o <<= 1) {
            int t = __shfl_up_sync(FULLM, x, o);
            if (lane >= o) x += t;
        }
        if (lane == 31) s_wtot[wid] = x;
        __syncthreads();
        if (wid == 0) {
            int w = s_wtot[lane];
            int y = w;
            #pragma unroll
            for (int o = 1; o < 32; o <<= 1) {
                int t = __shfl_up_sync(FULLM, y, o);
                if (lane >= o) y += t;
            }
            s_wtot[lane] = y - w;
            if (lane == 31) s_wtot[32] = y;
        }
        __syncthreads();
        int excl = s_carry + s_wtot[wid] + (x - v);
        if (i < NN) { g_rowptr[i] = excl; g_cursor[i] = excl; }
        int btot = s_wtot[32];
        __syncthreads();
        if (tid == 0) s_carry += btot;
        __syncthreads();
    }
    if (tid == 0) g_rowptr[NN] = s_carry;
}

// ---------------- transform / alpha device functions ------------------------
template <int DIN, int DOUT>
__device__ __forceinline__ void dev_transform(float* s_buf, int blk,
                                              const float* __restrict__ W) {
    constexpr int HD = 6 * DOUT;
    constexpr int C4 = HD / 4;
    for (int i = threadIdx.x; i < DIN * HD; i += 256) {
        int k = i / DIN, d = i - k * DIN;
        s_buf[d * HD + k] = W[i];
    }
    __syncthreads();
    int t = blk * 256 + threadIdx.x;
    if (t >= (NN / 4) * C4) return;
    int c4 = t % C4, nb = t / C4;
    int n0 = nb * 4;
    const float4* x4 = g_hin4;
    const float4* w4 = reinterpret_cast<const float4*>(s_buf);
    float4 acc0 = {0,0,0,0}, acc1 = {0,0,0,0}, acc2 = {0,0,0,0}, acc3 = {0,0,0,0};
    #pragma unroll
    for (int dc = 0; dc < DIN / 4; dc++) {
        float4 xv0 = x4[(n0 + 0) * (DIN / 4) + dc];
        float4 xv1 = x4[(n0 + 1) * (DIN / 4) + dc];
        float4 xv2 = x4[(n0 + 2) * (DIN / 4) + dc];
        float4 xv3 = x4[(n0 + 3) * (DIN / 4) + dc];
        #pragma unroll
        for (int j = 0; j < 4; j++) {
            float4 wv = w4[(dc * 4 + j) * C4 + c4];
            fma4(acc0, wv, f4c(xv0, j));
            fma4(acc1, wv, f4c(xv1, j));
            fma4(acc2, wv, f4c(xv2, j));
            fma4(acc3, wv, f4c(xv3, j));
        }
    }
    g_h4[(n0 + 0) * C4 + c4] = acc0;
    g_h4[(n0 + 1) * C4 + c4] = acc1;
    g_h4[(n0 + 2) * C4 + c4] = acc2;
    g_h4[(n0 + 3) * C4 + c4] = acc3;
}

template <int DIN, int DOUT>
__device__ __forceinline__ void dev_alpha(float* s_buf, int blk,
                                          const float* __restrict__ W,
                                          const float* __restrict__ asv,
                                          const float* __restrict__ adv) {
    // fold attention vectors: wa[d][hh] (hh<6: src, hh>=6: dst)
    for (int i = threadIdx.x; i < 12 * DIN; i += 256) {
        int d = i / 12, hh = i - d * 12;
        int head = hh % 6;
        const float* av = (hh < 6 ? asv : adv) + head * DOUT;
        float s = 0.f;
        #pragma unroll
        for (int o = 0; o < DOUT; o++) s += av[o] * W[(head * DOUT + o) * DIN + d];
        s_buf[d * 12 + hh] = s;
    }
    __syncthreads();
    int t2 = blk * 256 + threadIdx.x;
    if (t2 >= NN * 12) return;
    int n = t2 / 12, hh = t2 - n * 12;
    const float* xr = reinterpret_cast<const float*>(g_hin4) + n * DIN;
    float acc = 0.f;
    #pragma unroll
    for (int d = 0; d < DIN; d++) acc += xr[d] * s_buf[d * 12 + hh];
    reinterpret_cast<float*>(g_ae4)[n * 16 + (hh < 6 ? hh : hh + 2)] = acc;
}

// ---------------- launch 2: scatter + layer-1 feat (fused) ------------------
#define NBT1 CDIV((NN / 4) * 48, 256)
#define NBA  CDIV(NN * 12, 256)
#define SCAT_BLOCKS CDIV(ET, 256)
__global__ __launch_bounds__(256) void k_scatter_feat1(const int* __restrict__ ei,
                                                       const float* __restrict__ W,
                                                       const float* __restrict__ asv,
                                                       const float* __restrict__ adv) {
    __shared__ float s_buf[16 * 192];
    if (blockIdx.x < NBT1) {
        dev_transform<16, 32>(s_buf, blockIdx.x, W);
    } else if (blockIdx.x < NBT1 + NBA) {
        dev_alpha<16, 32>(s_buf, blockIdx.x - NBT1, W, asv, adv);
    } else {
        int i = (blockIdx.x - NBT1 - NBA) * 256 + threadIdx.x;
        if (i >= ET) return;
        int s, d;
        if (i < EE) { s = ei[i]; d = ei[EE + i]; }
        else        { s = d = i - EE; }
        int pos = atomicAdd(&g_cursor[d], 1);
        g_csr[pos] = s;
    }
}

// ---------------- generic per-layer feat (layers 2-4) -----------------------
template <int DIN, int DOUT, bool ZERO_CURSOR>
__global__ __launch_bounds__(256) void k_feat(const float* __restrict__ W,
                                              const float* __restrict__ asv,
                                              const float* __restrict__ adv) {
    __shared__ float s_buf[DIN * 6 * DOUT];
    constexpr int NBT = CDIV((NN / 4) * (6 * DOUT / 4), 256);
    if (blockIdx.x < NBT) {
        dev_transform<DIN, DOUT>(s_buf, blockIdx.x, W);
    } else if (blockIdx.x < NBT + NBA) {
        dev_alpha<DIN, DOUT>(s_buf, blockIdx.x - NBT, W, asv, adv);
    } else if (ZERO_CURSOR) {
        int i = (blockIdx.x - NBT - NBA) * 256 + threadIdx.x;
        if (i < NN) g_cursor[i] = 0;
    }
}

// ---------------- fused GAT -------------------------------------------------
template <int DOUT>
__global__ __launch_bounds__(256) void k_gat(const float* __restrict__ bias,
                                             float* __restrict__ out) {
    constexpr int HD = 6 * DOUT;
    __shared__ float s_alpha[(DOUT > 2) ? 8 * 192 : 8];
    int w = threadIdx.x >> 5, lane = threadIdx.x & 31;
    int n = blockIdx.x * 8 + w;           // grid = NN/8 exactly
    int start = g_rowptr[n], end = g_rowptr[n + 1];
    int deg = end - start;

    const float4* ae4 = g_ae4;
    const float*  aef = reinterpret_cast<const float*>(g_ae4);
    const float4* gh4 = g_h4;
    float4 d03 = ae4[n * 4 + 2];
    float4 d45 = ae4[n * 4 + 3];
    float adh[6] = {d03.x, d03.y, d03.z, d03.w, d45.x, d45.y};
    float* sw = s_alpha + ((DOUT > 2) ? w * 192 : 0);

    float4 acc0 = {0,0,0,0}, acc1 = {0,0,0,0};

    if (deg <= 32) {
        // ========== fast path: lane-per-edge cached softmax ==========
        int s = 0;
        bool act = lane < deg;
        if (act) s = g_csr[start + lane];
        float ev[6];
        if (act) {
            float4 a03 = ae4[s * 4 + 0];
            float4 a45 = ae4[s * 4 + 1];
            ev[0] = lrelu(a03.x + adh[0]); ev[1] = lrelu(a03.y + adh[1]);
            ev[2] = lrelu(a03.z + adh[2]); ev[3] = lrelu(a03.w + adh[3]);
            ev[4] = lrelu(a45.x + adh[4]); ev[5] = lrelu(a45.y + adh[5]);
        } else {
            #pragma unroll
            for (int h = 0; h < 6; h++) ev[h] = -1e30f;
        }
        float M[6];
        #pragma unroll
        for (int h = 0; h < 6; h++) M[h] = ev[h];
        #pragma unroll
        for (int h = 0; h < 6; h++)
            #pragma unroll
            for (int o = 16; o > 0; o >>= 1)
                M[h] = fmaxf(M[h], __shfl_xor_sync(FULLM, M[h], o));
        float p[6], S[6];
        #pragma unroll
        for (int h = 0; h < 6; h++) { p[h] = __expf(ev[h] - M[h]); S[h] = p[h]; }
        #pragma unroll
        for (int h = 0; h < 6; h++)
            #pragma unroll
            for (int o = 16; o > 0; o >>= 1)
                S[h] += __shfl_xor_sync(FULLM, S[h], o);
        float al[6];
        #pragma unroll
        for (int h = 0; h < 6; h++) al[h] = p[h] * (1.f / S[h]);

        if constexpr (DOUT == 2) {
            float4 v0 = {0,0,0,0}, v1 = {0,0,0,0}, v2 = {0,0,0,0};
            if (act) {
                const float4* hp = gh4 + s * 3;
                v0 = hp[0]; v1 = hp[1]; v2 = hp[2];
            }
            float acc[12];
            acc[0] = v0.x * al[0]; acc[1]  = v0.y * al[0];
            acc[2] = v0.z * al[1]; acc[3]  = v0.w * al[1];
            acc[4] = v1.x * al[2]; acc[5]  = v1.y * al[2];
            acc[6] = v1.z * al[3]; acc[7]  = v1.w * al[3];
            acc[8] = v2.x * al[4]; acc[9]  = v2.y * al[4];
            acc[10]= v2.z * al[5]; acc[11] = v2.w * al[5];
            #pragma unroll
            for (int k = 0; k < 12; k++)
                #pragma unroll
                for (int o = 16; o > 0; o >>= 1)
                    acc[k] += __shfl_xor_sync(FULLM, acc[k], o);
            if (lane < 2) {
                float s6 = acc[lane] + acc[2 + lane] + acc[4 + lane] +
                           acc[6 + lane] + acc[8 + lane] + acc[10 + lane];
                out[n * 2 + lane] = selu_f(s6 * (1.f / 6.f) + bias[lane]);
            }
            return;
        }

        // stage per-edge alphas in smem: [edge j][head h]
        #pragma unroll
        for (int h = 0; h < 6; h++) sw[lane * 6 + h] = al[h];
        __syncwarp();

        if constexpr (DOUT == 32) {
            int h0 = lane >> 3;
            int h1i = (lane < 16) ? 4 + (lane >> 3) : 0;
            bool q = lane < 16;
            for (int j = 0; j < deg; j += 2) {
                int s0 = __shfl_sync(FULLM, s, j);
                int s1 = __shfl_sync(FULLM, s, j + 1);
                float a00 = sw[j * 6 + h0];
                float a01 = sw[j * 6 + h1i];
                float a10 = sw[(j + 1) * 6 + h0];
                float a11 = sw[(j + 1) * 6 + h1i];
                const float4* hp0 = gh4 + (size_t)s0 * 48;
                const float4* hp1 = gh4 + (size_t)s1 * 48;
                float4 p0 = hp0[lane];
                float4 p1 = hp1[lane];
                float4 q0 = {0,0,0,0}, q1 = {0,0,0,0};
                if (q) { q0 = hp0[32 + lane]; q1 = hp1[32 + lane]; }
                fma4(acc0, p0, a00); fma4(acc1, q0, a01);
                fma4(acc0, p1, a10); fma4(acc1, q1, a11);
            }
        } else { // DOUT == 16
            bool actl = lane < 24;
            int h0i = actl ? (lane >> 2) : 0;
            for (int j = 0; j < deg; j += 2) {
                int s0 = __shfl_sync(FULLM, s, j);
                int s1 = __shfl_sync(FULLM, s, j + 1);
                float a0 = sw[j * 6 + h0i];
                float a1 = sw[(j + 1) * 6 + h0i];
                float4 p0 = {0,0,0,0}, p1 = {0,0,0,0};
                if (actl) {
                    p0 = gh4[(size_t)s0 * 24 + lane];
                    p1 = gh4[(size_t)s1 * 24 + lane];
                }
                fma4(acc0, p0, a0); fma4(acc0, p1, a1);
            }
        }
    } else {
        // ========== slow path (deg > 32, rare) ==========
        float M[6];
        #pragma unroll
        for (int h = 0; h < 6; h++) M[h] = -1e30f;
        for (int j = start + lane; j < end; j += 32) {
            int s = g_csr[j];
            float4 a03 = ae4[s * 4 + 0], a45 = ae4[s * 4 + 1];
            float ev[6] = {lrelu(a03.x + adh[0]), lrelu(a03.y + adh[1]),
                           lrelu(a03.z + adh[2]), lrelu(a03.w + adh[3]),
                           lrelu(a45.x + adh[4]), lrelu(a45.y + adh[5])};
            #pragma unroll
            for (int h = 0; h < 6; h++) M[h] = fmaxf(M[h], ev[h]);
        }
        #pragma unroll
        for (int h = 0; h < 6; h++)
            #pragma unroll
            for (int o = 16; o > 0; o >>= 1)
                M[h] = fmaxf(M[h], __shfl_xor_sync(FULLM, M[h], o));
        float S[6];
        #pragma unroll
        for (int h = 0; h < 6; h++) S[h] = 0.f;
        for (int j = start + lane; j < end; j += 32) {
            int s = g_csr[j];
            float4 a03 = ae4[s * 4 + 0], a45 = ae4[s * 4 + 1];
            float ev[6] = {lrelu(a03.x + adh[0]), lrelu(a03.y + adh[1]),
                           lrelu(a03.z + adh[2]), lrelu(a03.w + adh[3]),
                           lrelu(a45.x + adh[4]), lrelu(a45.y + adh[5])};
            #pragma unroll
            for (int h = 0; h < 6; h++) S[h] += __expf(ev[h] - M[h]);
        }
        #pragma unroll
        for (int h = 0; h < 6; h++)
            #pragma unroll
            for (int o = 16; o > 0; o >>= 1)
                S[h] += __shfl_xor_sync(FULLM, S[h], o);
        float inv[6];
        #pragma unroll
        for (int h = 0; h < 6; h++) inv[h] = 1.f / S[h];

        if constexpr (DOUT == 2) {
            float acc[12];
            #pragma unroll
            for (int k = 0; k < 12; k++) acc[k] = 0.f;
            for (int j = start + lane; j < end; j += 32) {
                int s = g_csr[j];
                float4 a03 = ae4[s * 4 + 0], a45 = ae4[s * 4 + 1];
                float ev[6] = {lrelu(a03.x + adh[0]), lrelu(a03.y + adh[1]),
                               lrelu(a03.z + adh[2]), lrelu(a03.w + adh[3]),
                               lrelu(a45.x + adh[4]), lrelu(a45.y + adh[5])};
                float al[6];
                #pragma unroll
                for (int h = 0; h < 6; h++) al[h] = __expf(ev[h] - M[h]) * inv[h];
                const float4* hp = gh4 + s * 3;
                float4 v0 = hp[0], v1 = hp[1], v2 = hp[2];
                acc[0] += v0.x * al[0]; acc[1]  += v0.y * al[0];
                acc[2] += v0.z * al[1]; acc[3]  += v0.w * al[1];
                acc[4] += v1.x * al[2]; acc[5]  += v1.y * al[2];
                acc[6] += v1.z * al[3]; acc[7]  += v1.w * al[3];
                acc[8] += v2.x * al[4]; acc[9]  += v2.y * al[4];
                acc[10]+= v2.z * al[5]; acc[11] += v2.w * al[5];
            }
            #pragma unroll
            for (int k = 0; k < 12; k++)
                #pragma unroll
                for (int o = 16; o > 0; o >>= 1)
                    acc[k] += __shfl_xor_sync(FULLM, acc[k], o);
            if (lane < 2) {
                float s6 = acc[lane] + acc[2 + lane] + acc[4 + lane] +
                           acc[6 + lane] + acc[8 + lane] + acc[10 + lane];
                out[n * 2 + lane] = selu_f(s6 * (1.f / 6.f) + bias[lane]);
            }
            return;
        }

        float m_sel = 0.f, inv_sel = 0.f, ad_sel = 0.f;
        #pragma unroll
        for (int h = 0; h < 6; h++)
            if (lane == h) { m_sel = M[h]; inv_sel = inv[h]; ad_sel = adh[h]; }

        if constexpr (DOUT == 32) {
            int src0 = lane >> 3, src1 = 4 + (lane >> 3);
            for (int j = start; j < end; j++) {
                int s0 = g_csr[j];
                float a = 0.f;
                if (lane < 6) {
                    float e = lrelu(aef[s0 * 16 + lane] + ad_sel);
                    a = __expf(e - m_sel) * inv_sel;
                }
                const float4* hp = gh4 + (size_t)s0 * 48;
                float4 p0 = hp[lane];
                float4 q0 = {0,0,0,0};
                if (lane < 16) q0 = hp[32 + lane];
                float av = __shfl_sync(FULLM, a, src0);
                float aw = __shfl_sync(FULLM, a, src1);
                fma4(acc0, p0, av);
                fma4(acc1, q0, aw);
            }
        } else { // DOUT == 16
            int srch = (lane >> 2) & 7;
            for (int j = start; j < end; j++) {
                int s0 = g_csr[j];
                float a = 0.f;
                if (lane < 6) {
                    float e = lrelu(aef[s0 * 16 + lane] + ad_sel);
                    a = __expf(e - m_sel) * inv_sel;
                }
                float4 p0 = {0,0,0,0};
                if (lane < 24) p0 = gh4[(size_t)s0 * 24 + lane];
                float av = __shfl_sync(FULLM, a, srch);
                fma4(acc0, p0, av);
            }
        }
    }

    // ---- common epilogue: head mean + bias + SELU ----
    __syncwarp();
    if constexpr (DOUT == 32) {
        sw[lane * 4 + 0] = acc0.x; sw[lane * 4 + 1] = acc0.y;
        sw[lane * 4 + 2] = acc0.z; sw[lane * 4 + 3] = acc0.w;
        if (lane < 16) {
            sw[128 + lane * 4 + 0] = acc1.x; sw[128 + lane * 4 + 1] = acc1.y;
            sw[128 + lane * 4 + 2] = acc1.z; sw[128 + lane * 4 + 3] = acc1.w;
        }
        __syncwarp();
        float o0 = sw[lane] + sw[32 + lane] + sw[64 + lane] +
                   sw[96 + lane] + sw[128 + lane] + sw[160 + lane];
        out[n * 32 + lane] = selu_f(o0 * (1.f / 6.f) + bias[lane]);
    } else if constexpr (DOUT == 16) {
        if (lane < 24) {
            sw[lane * 4 + 0] = acc0.x; sw[lane * 4 + 1] = acc0.y;
            sw[lane * 4 + 2] = acc0.z; sw[lane * 4 + 3] = acc0.w;
        }
        __syncwarp();
        if (lane < 16) {
            float o0 = sw[lane] + sw[16 + lane] + sw[32 + lane] +
                       sw[48 + lane] + sw[64 + lane] + sw[80 + lane];
            out[n * 16 + lane] = selu_f(o0 * (1.f / 6.f) + bias[lane]);
        }
    }
}

// ---------------- host launcher ---------------------------------------------
extern "C" void kernel_launch(void* const* d_in, const int* in_sizes, int n_in,
                              void* d_out, int out_size) {
    (void)in_sizes; (void)n_in; (void)out_size;
    const float* x     = (const float*)d_in[0];
    const int*   ei    = (const int*)d_in[1];
    const float* lin_w = (const float*)d_in[2];
    const float* lin_b = (const float*)d_in[3];
    const float* W[4]  = { (const float*)d_in[4],  (const float*)d_in[8],
                           (const float*)d_in[12], (const float*)d_in[16] };
    const float* AS[4] = { (const float*)d_in[5],  (const float*)d_in[9],
                           (const float*)d_in[13], (const float*)d_in[17] };
    const float* AD[4] = { (const float*)d_in[6],  (const float*)d_in[10],
                           (const float*)d_in[14], (const float*)d_in[18] };
    const float* B[4]  = { (const float*)d_in[7],  (const float*)d_in[11],
                           (const float*)d_in[15], (const float*)d_in[19] };
    float* out = (float*)d_out;

    float* g_hin_ptr = nullptr;
    cudaGetSymbolAddress((void**)&g_hin_ptr, g_hin4);

    const int gat_blocks = NN / 8;

    // 0: count + lin0  (cursor is zero: zero-init on first call, reset by feat4 after)
    k_count_lin0<<<CNT_BLOCKS + LIN0_BLOCKS, 256>>>(ei, x, lin_w, lin_b);
    // 1: scan
    k_scan<<<1, 1024>>>();
    // 2: scatter + layer-1 transform + alpha
    k_scatter_feat1<<<NBT1 + NBA + SCAT_BLOCKS, 256>>>(ei, W[0], AS[0], AD[0]);
    // 3: gat layer 1   <- ncu capture target
    k_gat<32><<<gat_blocks, 256>>>(B[0], g_hin_ptr);
    // 4-5: layer 2
    k_feat<32, 32, false><<<CDIV((NN / 4) * 48, 256) + NBA, 256>>>(W[1], AS[1], AD[1]);
    k_gat<32><<<gat_blocks, 256>>>(B[1], g_hin_ptr);
    // 6-7: layer 3
    k_feat<32, 16, false><<<CDIV((NN / 4) * 24, 256) + NBA, 256>>>(W[2], AS[2], AD[2]);
    k_gat<16><<<gat_blocks, 256>>>(B[2], g_hin_ptr);
    // 8-9: layer 4 (+cursor re-zero for next call)
    k_feat<16, 2, true><<<CDIV((NN / 4) * 3, 256) + NBA + CDIV(NN, 256), 256>>>(W[3], AS[3], AD[3]);
    k_gat<2><<<gat_blocks, 256>>>(B[3], out);
}

// round 6
// speedup vs baseline: 1.3934x; 1.1015x over previous
#include <cuda_runtime.h>
#include <cuda_fp16.h>

#define NN 50000
#define EE 800000
#define ET (EE + NN)   // edges + self loops
#define FULLM 0xffffffffu

__host__ __device__ constexpr int CDIV(int a, int b) { return (a + b - 1) / b; }

// ---------------- scratch (static __device__ globals; no allocs) -------------
__device__ int    g_rowptr[NN + 1];
__device__ int    g_cursor[NN];          // zero at call start (invariant)
__device__ int    g_csr[ET];
__device__ float4 g_hin4[NN * 8];        // node features [n][din] fp32, din<=32
__device__ __align__(128) __half g_hh[NN * 192];  // transformed features, fp16
__device__ float4 g_ae4[NN * 4];         // [n][16]: 0..5 src logits, 8..13 dst logits

__device__ __forceinline__ float selu_f(float x) {
    const float sc = 1.0507009873554805f;
    const float al = 1.6732632423543772f;
    return x > 0.f ? sc * x : sc * al * (__expf(x) - 1.f);
}
__device__ __forceinline__ float lrelu(float x) { return x > 0.f ? x : 0.2f * x; }
__device__ __forceinline__ float f4c(const float4& v, int j) {
    return j == 0 ? v.x : j == 1 ? v.y : j == 2 ? v.z : v.w;
}
__device__ __forceinline__ void fma4(float4& a, const float4& v, float s) {
    a.x += v.x * s; a.y += v.y * s; a.z += v.z * s; a.w += v.w * s;
}
__device__ __forceinline__ uint2 f4_to_h4(float4 a) {
    __half2 lo = __floats2half2_rn(a.x, a.y);
    __half2 hi = __floats2half2_rn(a.z, a.w);
    uint2 r;
    r.x = *reinterpret_cast<unsigned*>(&lo);
    r.y = *reinterpret_cast<unsigned*>(&hi);
    return r;
}
// accumulate 8 fp16 dims (one uint4) scaled by al into two float4 accumulators
__device__ __forceinline__ void hfma8(float4& a0, float4& a1, uint4 u, float al) {
    __half2 h0 = *reinterpret_cast<__half2*>(&u.x);
    __half2 h1 = *reinterpret_cast<__half2*>(&u.y);
    __half2 h2 = *reinterpret_cast<__half2*>(&u.z);
    __half2 h3 = *reinterpret_cast<__half2*>(&u.w);
    float2 f0 = __half22float2(h0), f1 = __half22float2(h1);
    float2 f2 = __half22float2(h2), f3 = __half22float2(h3);
    a0.x += f0.x * al; a0.y += f0.y * al; a0.z += f1.x * al; a0.w += f1.y * al;
    a1.x += f2.x * al; a1.y += f2.y * al; a1.z += f3.x * al; a1.w += f3.y * al;
}

// ---------------- launch 0: degree count + initial linear -------------------
#define CNT_BLOCKS  CDIV(EE, 256)
#define LIN0_BLOCKS CDIV(NN * 16, 256)
__global__ __launch_bounds__(256) void k_count_lin0(const int* __restrict__ ei,
                                                    const float* __restrict__ x,
                                                    const float* __restrict__ lw,
                                                    const float* __restrict__ lb) {
    if (blockIdx.x < CNT_BLOCKS) {
        int i = blockIdx.x * 256 + threadIdx.x;
        if (i < EE) atomicAdd(&g_cursor[ei[EE + i]], 1);
    } else {
        int i = (blockIdx.x - CNT_BLOCKS) * 256 + threadIdx.x;
        if (i >= NN * 16) return;
        int n = i >> 4, c = i & 15;
        const float* xr = x + n * 10;
        const float* wr = lw + c * 10;
        float acc = lb[c];
        #pragma unroll
        for (int d = 0; d < 10; d++) acc += xr[d] * wr[d];
        reinterpret_cast<float*>(g_hin4)[i] = selu_f(acc);
    }
}

// ---------------- launch 1: scan (adds self-loop +1, resets cursor) ---------
__global__ void k_scan() {
    __shared__ int s_wtot[33];
    __shared__ int s_carry;
    int tid = threadIdx.x, lane = tid & 31, wid = tid >> 5;
    if (tid == 0) s_carry = 0;
    __syncthreads();
    for (int base = 0; base < NN; base += 1024) {
        int i = base + tid;
        int v = (i < NN) ? (g_cursor[i] + 1) : 0;   // +1 self loop
        int x = v;
        #pragma unroll
        for (int o = 1; o < 32; o <<= 1) {
            int t = __shfl_up_sync(FULLM, x, o);
            if (lane >= o) x += t;
        }
        if (lane == 31) s_wtot[wid] = x;
        __syncthreads();
        if (wid == 0) {
            int w = s_wtot[lane];
            int y = w;
            #pragma unroll
            for (int o = 1; o < 32; o <<= 1) {
                int t = __shfl_up_sync(FULLM, y, o);
                if (lane >= o) y += t;
            }
            s_wtot[lane] = y - w;
            if (lane == 31) s_wtot[32] = y;
        }
        __syncthreads();
        int excl = s_carry + s_wtot[wid] + (x - v);
        if (i < NN) { g_rowptr[i] = excl; g_cursor[i] = excl; }
        int btot = s_wtot[32];
        __syncthreads();
        if (tid == 0) s_carry += btot;
        __syncthreads();
    }
    if (tid == 0) g_rowptr[NN] = s_carry;
}

// ---------------- transform / alpha device functions ------------------------
template <int DIN, int DOUT, int STRIDE>
__device__ __forceinline__ void dev_transform(float* s_buf, int blk,
                                              const float* __restrict__ W) {
    constexpr int HD = 6 * DOUT;
    constexpr int C4 = HD / 4;
    constexpr int C4S = STRIDE / 4;
    for (int i = threadIdx.x; i < DIN * HD; i += 256) {
        int k = i / DIN, d = i - k * DIN;
        s_buf[d * HD + k] = W[i];
    }
    __syncthreads();
    int t = blk * 256 + threadIdx.x;
    if (t >= (NN / 4) * C4S) return;
    int c4 = t % C4S, nb = t / C4S;
    int n0 = nb * 4;
    float4 acc0 = {0,0,0,0}, acc1 = {0,0,0,0}, acc2 = {0,0,0,0}, acc3 = {0,0,0,0};
    if (c4 < C4) {
        const float4* x4 = g_hin4;
        const float4* w4 = reinterpret_cast<const float4*>(s_buf);
        #pragma unroll
        for (int dc = 0; dc < DIN / 4; dc++) {
            float4 xv0 = x4[(n0 + 0) * (DIN / 4) + dc];
            float4 xv1 = x4[(n0 + 1) * (DIN / 4) + dc];
            float4 xv2 = x4[(n0 + 2) * (DIN / 4) + dc];
            float4 xv3 = x4[(n0 + 3) * (DIN / 4) + dc];
            #pragma unroll
            for (int j = 0; j < 4; j++) {
                float4 wv = w4[(dc * 4 + j) * C4 + c4];
                fma4(acc0, wv, f4c(xv0, j));
                fma4(acc1, wv, f4c(xv1, j));
                fma4(acc2, wv, f4c(xv2, j));
                fma4(acc3, wv, f4c(xv3, j));
            }
        }
    }
    __half* hb = g_hh;
    *reinterpret_cast<uint2*>(hb + (size_t)(n0 + 0) * STRIDE + c4 * 4) = f4_to_h4(acc0);
    *reinterpret_cast<uint2*>(hb + (size_t)(n0 + 1) * STRIDE + c4 * 4) = f4_to_h4(acc1);
    *reinterpret_cast<uint2*>(hb + (size_t)(n0 + 2) * STRIDE + c4 * 4) = f4_to_h4(acc2);
    *reinterpret_cast<uint2*>(hb + (size_t)(n0 + 3) * STRIDE + c4 * 4) = f4_to_h4(acc3);
}

template <int DIN, int DOUT>
__device__ __forceinline__ void dev_alpha(float* s_buf, int blk,
                                          const float* __restrict__ W,
                                          const float* __restrict__ asv,
                                          const float* __restrict__ adv) {
    for (int i = threadIdx.x; i < 12 * DIN; i += 256) {
        int d = i / 12, hh = i - d * 12;
        int head = hh % 6;
        const float* av = (hh < 6 ? asv : adv) + head * DOUT;
        float s = 0.f;
        #pragma unroll
        for (int o = 0; o < DOUT; o++) s += av[o] * W[(head * DOUT + o) * DIN + d];
        s_buf[d * 12 + hh] = s;
    }
    __syncthreads();
    int t2 = blk * 256 + threadIdx.x;
    if (t2 >= NN * 12) return;
    int n = t2 / 12, hh = t2 - n * 12;
    const float* xr = reinterpret_cast<const float*>(g_hin4) + n * DIN;
    float acc = 0.f;
    #pragma unroll
    for (int d = 0; d < DIN; d++) acc += xr[d] * s_buf[d * 12 + hh];
    reinterpret_cast<float*>(g_ae4)[n * 16 + (hh < 6 ? hh : hh + 2)] = acc;
}

// ---------------- launch 2: scatter + layer-1 feat (fused) ------------------
#define NBT1 CDIV((NN / 4) * 48, 256)
#define NBA  CDIV(NN * 12, 256)
#define SCAT_BLOCKS CDIV(ET, 256)
__global__ __launch_bounds__(256) void k_scatter_feat1(const int* __restrict__ ei,
                                                       const float* __restrict__ W,
                                                       const float* __restrict__ asv,
                                                       const float* __restrict__ adv) {
    __shared__ float s_buf[16 * 192];
    if (blockIdx.x < NBT1) {
        dev_transform<16, 32, 192>(s_buf, blockIdx.x, W);
    } else if (blockIdx.x < NBT1 + NBA) {
        dev_alpha<16, 32>(s_buf, blockIdx.x - NBT1, W, asv, adv);
    } else {
        int i = (blockIdx.x - NBT1 - NBA) * 256 + threadIdx.x;
        if (i >= ET) return;
        int s, d;
        if (i < EE) { s = ei[i]; d = ei[EE + i]; }
        else        { s = d = i - EE; }
        int pos = atomicAdd(&g_cursor[d], 1);
        g_csr[pos] = s;
    }
}

// ---------------- generic per-layer feat (layers 2-4) -----------------------
template <int DIN, int DOUT, int STRIDE, bool ZERO_CURSOR>
__global__ __launch_bounds__(256) void k_feat(const float* __restrict__ W,
                                              const float* __restrict__ asv,
                                              const float* __restrict__ adv) {
    __shared__ float s_buf[DIN * 6 * DOUT];
    constexpr int NBT = CDIV((NN / 4) * (STRIDE / 4), 256);
    if (blockIdx.x < NBT) {
        dev_transform<DIN, DOUT, STRIDE>(s_buf, blockIdx.x, W);
    } else if (blockIdx.x < NBT + NBA) {
        dev_alpha<DIN, DOUT>(s_buf, blockIdx.x - NBT, W, asv, adv);
    } else if (ZERO_CURSOR) {
        int i = (blockIdx.x - NBT - NBA) * 256 + threadIdx.x;
        if (i < NN) g_cursor[i] = 0;
    }
}

// ---------------- fused GAT -------------------------------------------------
template <int DOUT>
__global__ __launch_bounds__(256) void k_gat(const float* __restrict__ bias,
                                             float* __restrict__ out) {
    __shared__ float s_red[(DOUT > 2) ? 8 * 192 : 8];
    int w = threadIdx.x >> 5, lane = threadIdx.x & 31;
    int n = blockIdx.x * 8 + w;           // grid = NN/8 exactly
    int start = g_rowptr[n], end = g_rowptr[n + 1];
    int deg = end - start;

    const float4* ae4 = g_ae4;
    const float*  aef = reinterpret_cast<const float*>(g_ae4);
    float4 d03 = ae4[n * 4 + 2];
    float4 d45 = ae4[n * 4 + 3];
    float adh[6] = {d03.x, d03.y, d03.z, d03.w, d45.x, d45.y};
    float* sw = s_red + ((DOUT > 2) ? w * 192 : 0);
    const uint4* gh = reinterpret_cast<const uint4*>(g_hh);

    // ================= DOUT == 2 (HD=12, stride 16 halves) =================
    if constexpr (DOUT == 2) {
        float acc[12];
        #pragma unroll
        for (int k = 0; k < 12; k++) acc[k] = 0.f;
        if (deg <= 32) {
            int s = 0; bool act = lane < deg;
            if (act) s = g_csr[start + lane];
            float p[6], S[6];
            if (act) {
                float4 a03 = ae4[s * 4 + 0], a45 = ae4[s * 4 + 1];
                p[0] = __expf(lrelu(a03.x + adh[0]));
                p[1] = __expf(lrelu(a03.y + adh[1]));
                p[2] = __expf(lrelu(a03.z + adh[2]));
                p[3] = __expf(lrelu(a03.w + adh[3]));
                p[4] = __expf(lrelu(a45.x + adh[4]));
                p[5] = __expf(lrelu(a45.y + adh[5]));
            } else {
                #pragma unroll
                for (int h = 0; h < 6; h++) p[h] = 0.f;
            }
            #pragma unroll
            for (int h = 0; h < 6; h++) S[h] = p[h];
            #pragma unroll
            for (int h = 0; h < 6; h++)
                #pragma unroll
                for (int o = 16; o > 0; o >>= 1)
                    S[h] += __shfl_xor_sync(FULLM, S[h], o);
            float al[6];
            #pragma unroll
            for (int h = 0; h < 6; h++) al[h] = p[h] * (1.f / S[h]);
            if (act) {
                const uint4* hp = gh + s * 2;
                uint4 u0 = hp[0], u1 = hp[1];
                __half2* h0 = reinterpret_cast<__half2*>(&u0);
                __half2* h1 = reinterpret_cast<__half2*>(&u1);
                float2 f;
                f = __half22float2(h0[0]); acc[0] = f.x * al[0]; acc[1] = f.y * al[0];
                f = __half22float2(h0[1]); acc[2] = f.x * al[1]; acc[3] = f.y * al[1];
                f = __half22float2(h0[2]); acc[4] = f.x * al[2]; acc[5] = f.y * al[2];
                f = __half22float2(h0[3]); acc[6] = f.x * al[3]; acc[7] = f.y * al[3];
                f = __half22float2(h1[0]); acc[8] = f.x * al[4]; acc[9] = f.y * al[4];
                f = __half22float2(h1[1]); acc[10] = f.x * al[5]; acc[11] = f.y * al[5];
            }
        } else {
            // slow path
            float S[6];
            #pragma unroll
            for (int h = 0; h < 6; h++) S[h] = 0.f;
            for (int j = start + lane; j < end; j += 32) {
                int s = g_csr[j];
                float4 a03 = ae4[s * 4 + 0], a45 = ae4[s * 4 + 1];
                S[0] += __expf(lrelu(a03.x + adh[0]));
                S[1] += __expf(lrelu(a03.y + adh[1]));
                S[2] += __expf(lrelu(a03.z + adh[2]));
                S[3] += __expf(lrelu(a03.w + adh[3]));
                S[4] += __expf(lrelu(a45.x + adh[4]));
                S[5] += __expf(lrelu(a45.y + adh[5]));
            }
            #pragma unroll
            for (int h = 0; h < 6; h++)
                #pragma unroll
                for (int o = 16; o > 0; o >>= 1)
                    S[h] += __shfl_xor_sync(FULLM, S[h], o);
            float inv[6];
            #pragma unroll
            for (int h = 0; h < 6; h++) inv[h] = 1.f / S[h];
            for (int j = start + lane; j < end; j += 32) {
                int s = g_csr[j];
                float4 a03 = ae4[s * 4 + 0], a45 = ae4[s * 4 + 1];
                float al[6];
                al[0] = __expf(lrelu(a03.x + adh[0])) * inv[0];
                al[1] = __expf(lrelu(a03.y + adh[1])) * inv[1];
                al[2] = __expf(lrelu(a03.z + adh[2])) * inv[2];
                al[3] = __expf(lrelu(a03.w + adh[3])) * inv[3];
                al[4] = __expf(lrelu(a45.x + adh[4])) * inv[4];
                al[5] = __expf(lrelu(a45.y + adh[5])) * inv[5];
                const uint4* hp = gh + s * 2;
                uint4 u0 = hp[0], u1 = hp[1];
                __half2* h0 = reinterpret_cast<__half2*>(&u0);
                __half2* h1 = reinterpret_cast<__half2*>(&u1);
                float2 f;
                f = __half22float2(h0[0]); acc[0] += f.x * al[0]; acc[1] += f.y * al[0];
                f = __half22float2(h0[1]); acc[2] += f.x * al[1]; acc[3] += f.y * al[1];
                f = __half22float2(h0[2]); acc[4] += f.x * al[2]; acc[5] += f.y * al[2];
                f = __half22float2(h0[3]); acc[6] += f.x * al[3]; acc[7] += f.y * al[3];
                f = __half22float2(h1[0]); acc[8] += f.x * al[4]; acc[9] += f.y * al[4];
                f = __half22float2(h1[1]); acc[10] += f.x * al[5]; acc[11] += f.y * al[5];
            }
        }
        #pragma unroll
        for (int k = 0; k < 12; k++)
            #pragma unroll
            for (int o = 16; o > 0; o >>= 1)
                acc[k] += __shfl_xor_sync(FULLM, acc[k], o);
        if (lane < 2) {
            float s6 = acc[lane] + acc[2 + lane] + acc[4 + lane] +
                       acc[6 + lane] + acc[8 + lane] + acc[10 + lane];
            out[n * 2 + lane] = selu_f(s6 * (1.f / 6.f) + bias[lane]);
        }
        return;
    }

    // ================= DOUT == 32 / 16 =================
    bool actl = lane < 24;
    // DOUT==32: lane owns dims [lane*8, +8), head = lane/4
    // DOUT==16: 2 edges x 12 lanes; ll owns dims [ll*8, +8), head = ll/2
    int hidx, ll = 0, eo = 0;
    if constexpr (DOUT == 32) {
        hidx = actl ? (lane >> 2) : 0;
    } else {
        ll = actl ? (lane % 12) : 0;
        eo = actl ? (lane / 12) : 0;
        hidx = ll >> 1;
    }
    constexpr int NU4 = (DOUT == 32) ? 24 : 12;   // uint4 per node row
    float4 acc0 = {0,0,0,0}, acc1 = {0,0,0,0};

    if (deg <= 32) {
        // ---- fast path: lane-per-edge softmax (no max shift) ----
        int s = 0; bool act = lane < deg;
        if (act) s = g_csr[start + lane];
        float p[6], S[6];
        if (act) {
            float4 a03 = ae4[s * 4 + 0], a45 = ae4[s * 4 + 1];
            p[0] = __expf(lrelu(a03.x + adh[0]));
            p[1] = __expf(lrelu(a03.y + adh[1]));
            p[2] = __expf(lrelu(a03.z + adh[2]));
            p[3] = __expf(lrelu(a03.w + adh[3]));
            p[4] = __expf(lrelu(a45.x + adh[4]));
            p[5] = __expf(lrelu(a45.y + adh[5]));
        } else {
            #pragma unroll
            for (int h = 0; h < 6; h++) p[h] = 0.f;
        }
        #pragma unroll
        for (int h = 0; h < 6; h++) S[h] = p[h];
        #pragma unroll
        for (int h = 0; h < 6; h++)
            #pragma unroll
            for (int o = 16; o > 0; o >>= 1)
                S[h] += __shfl_xor_sync(FULLM, S[h], o);
        // stage alphas: sw[edge*6 + head]
        #pragma unroll
        for (int h = 0; h < 6; h++) sw[lane * 6 + h] = p[h] * (1.f / S[h]);
        __syncwarp();

        if constexpr (DOUT == 32) {
            for (int j = 0; j < deg; j += 2) {
                int s0 = __shfl_sync(FULLM, s, j);
                int s1 = __shfl_sync(FULLM, s, j + 1);
                float a0 = sw[j * 6 + hidx];
                float a1 = sw[(j + 1) * 6 + hidx];
                uint4 v0 = {0,0,0,0}, v1 = {0,0,0,0};
                if (actl) {
                    v0 = gh[(size_t)s0 * NU4 + lane];
                    v1 = gh[(size_t)s1 * NU4 + lane];
                } else { a0 = 0.f; a1 = 0.f; }
                hfma8(acc0, acc1, v0, a0);
                hfma8(acc0, acc1, v1, a1);
            }
        } else { // DOUT == 16: 2 edges per iter, 12 lanes each
            for (int j = 0; j < deg; j += 2) {
                int js = j + eo;                    // <= 31 for active lanes
                int s_sel = __shfl_sync(FULLM, s, js & 31);
                float a = actl ? sw[js * 6 + hidx] : 0.f;
                uint4 v = {0,0,0,0};
                if (actl) v = gh[(size_t)s_sel * NU4 + ll];
                hfma8(acc0, acc1, v, a);
            }
        }
    } else {
        // ---- slow path (deg > 32, rare) ----
        float S[6];
        #pragma unroll
        for (int h = 0; h < 6; h++) S[h] = 0.f;
        for (int j = start + lane; j < end; j += 32) {
            int s = g_csr[j];
            float4 a03 = ae4[s * 4 + 0], a45 = ae4[s * 4 + 1];
            S[0] += __expf(lrelu(a03.x + adh[0]));
            S[1] += __expf(lrelu(a03.y + adh[1]));
            S[2] += __expf(lrelu(a03.z + adh[2]));
            S[3] += __expf(lrelu(a03.w + adh[3]));
            S[4] += __expf(lrelu(a45.x + adh[4]));
            S[5] += __expf(lrelu(a45.y + adh[5]));
        }
        #pragma unroll
        for (int h = 0; h < 6; h++)
            #pragma unroll
            for (int o = 16; o > 0; o >>= 1)
                S[h] += __shfl_xor_sync(FULLM, S[h], o);
        float inv_sel = 0.f, ad_sel = 0.f;
        #pragma unroll
        for (int h = 0; h < 6; h++)
            if (hidx == h) { inv_sel = 1.f / S[h]; ad_sel = adh[h]; }

        bool act_agg = (DOUT == 32) ? actl : (actl && eo == 0);
        int dlane = (DOUT == 32) ? lane : ll;
        for (int j = start; j < end; j++) {
            int s0 = g_csr[j];
            float a = 0.f;
            uint4 v = {0,0,0,0};
            if (act_agg) {
                float e = lrelu(aef[s0 * 16 + hidx] + ad_sel);
                a = __expf(e) * inv_sel;
                v = gh[(size_t)s0 * NU4 + dlane];
            }
            hfma8(acc0, acc1, v, a);
        }
    }

    // ---- common epilogue: smem transpose, head mean + bias + SELU ----
    __syncwarp();
    if constexpr (DOUT == 32) {
        if (actl) {
            int b = lane * 8;
            sw[b + 0] = acc0.x; sw[b + 1] = acc0.y; sw[b + 2] = acc0.z; sw[b + 3] = acc0.w;
            sw[b + 4] = acc1.x; sw[b + 5] = acc1.y; sw[b + 6] = acc1.z; sw[b + 7] = acc1.w;
        }
        __syncwarp();
        float o0 = sw[lane] + sw[32 + lane] + sw[64 + lane] +
                   sw[96 + lane] + sw[128 + lane] + sw[160 + lane];
        out[n * 32 + lane] = selu_f(o0 * (1.f / 6.f) + bias[lane]);
    } else {
        if (actl) {
            int b = eo * 96 + ll * 8;
            sw[b + 0] = acc0.x; sw[b + 1] = acc0.y; sw[b + 2] = acc0.z; sw[b + 3] = acc0.w;
            sw[b + 4] = acc1.x; sw[b + 5] = acc1.y; sw[b + 6] = acc1.z; sw[b + 7] = acc1.w;
        }
        __syncwarp();
        if (lane < 16) {
            float o0 = 0.f;
            #pragma unroll
            for (int h = 0; h < 6; h++)
                o0 += sw[h * 16 + lane] + sw[96 + h * 16 + lane];
            out[n * 16 + lane] = selu_f(o0 * (1.f / 6.f) + bias[lane]);
        }
    }
}

// ---------------- host launcher ---------------------------------------------
extern "C" void kernel_launch(void* const* d_in, const int* in_sizes, int n_in,
                              void* d_out, int out_size) {
    (void)in_sizes; (void)n_in; (void)out_size;
    const float* x     = (const float*)d_in[0];
    const int*   ei    = (const int*)d_in[1];
    const float* lin_w = (const float*)d_in[2];
    const float* lin_b = (const float*)d_in[3];
    const float* W[4]  = { (const float*)d_in[4],  (const float*)d_in[8],
                           (const float*)d_in[12], (const float*)d_in[16] };
    const float* AS[4] = { (const float*)d_in[5],  (const float*)d_in[9],
                           (const float*)d_in[13], (const float*)d_in[17] };
    const float* AD[4] = { (const float*)d_in[6],  (const float*)d_in[10],
                           (const float*)d_in[14], (const float*)d_in[18] };
    const float* B[4]  = { (const float*)d_in[7],  (const float*)d_in[11],
                           (const float*)d_in[15], (const float*)d_in[19] };
    float* out = (float*)d_out;

    float* g_hin_ptr = nullptr;
    cudaGetSymbolAddress((void**)&g_hin_ptr, g_hin4);

    const int gat_blocks = NN / 8;

    // 0: count + lin0  (cursor zero: zero-init on first call, reset by feat4 after)
    k_count_lin0<<<CNT_BLOCKS + LIN0_BLOCKS, 256>>>(ei, x, lin_w, lin_b);
    // 1: scan
    k_scan<<<1, 1024>>>();
    // 2: scatter + layer-1 transform + alpha
    k_scatter_feat1<<<NBT1 + NBA + SCAT_BLOCKS, 256>>>(ei, W[0], AS[0], AD[0]);
    // 3: gat layer 1   <- ncu capture target
    k_gat<32><<<gat_blocks, 256>>>(B[0], g_hin_ptr);
    // 4-5: layer 2
    k_feat<32, 32, 192, false><<<CDIV((NN / 4) * 48, 256) + NBA, 256>>>(W[1], AS[1], AD[1]);
    k_gat<32><<<gat_blocks, 256>>>(B[1], g_hin_ptr);
    // 6-7: layer 3
    k_feat<32, 16, 96, false><<<CDIV((NN / 4) * 24, 256) + NBA, 256>>>(W[2], AS[2], AD[2]);
    k_gat<16><<<gat_blocks, 256>>>(B[2], g_hin_ptr);
    // 8-9: layer 4 (+cursor re-zero for next call)
    k_feat<16, 2, 16, true><<<CDIV((NN / 4) * 4, 256) + NBA + CDIV(NN, 256), 256>>>(W[3], AS[3], AD[3]);
    k_gat<2><<<gat_blocks, 256>>>(B[3], out);
}

// round 7
// speedup vs baseline: 1.5135x; 1.0861x over previous
#include <cuda_runtime.h>
#include <cuda_fp16.h>

#define NN 50000
#define EE 800000
#define ET (EE + NN)   // edges + self loops
#define FULLM 0xffffffffu

__host__ __device__ constexpr int CDIV(int a, int b) { return (a + b - 1) / b; }

// ---------------- scratch (static __device__ globals; no allocs) -------------
__device__ __align__(16) int g_rowptr[NN + 4];
__device__ __align__(16) int g_cursor[NN];       // zero at call start (invariant)
__device__ int    g_csr[ET];
__device__ float4 g_hin4[NN * 8];        // node features [n][din] fp32, din<=32
__device__ __align__(128) __half g_hh[NN * 192];  // transformed features, fp16
__device__ float4 g_ae4[NN * 4];         // [n][16]: 0..5 src logits, 8..13 dst logits

__device__ __forceinline__ float selu_f(float x) {
    const float sc = 1.0507009873554805f;
    const float al = 1.6732632423543772f;
    return x > 0.f ? sc * x : sc * al * (__expf(x) - 1.f);
}
__device__ __forceinline__ float lrelu(float x) { return x > 0.f ? x : 0.2f * x; }
__device__ __forceinline__ float f4c(const float4& v, int j) {
    return j == 0 ? v.x : j == 1 ? v.y : j == 2 ? v.z : v.w;
}
__device__ __forceinline__ void fma4(float4& a, const float4& v, float s) {
    a.x += v.x * s; a.y += v.y * s; a.z += v.z * s; a.w += v.w * s;
}
__device__ __forceinline__ uint2 f4_to_h4(float4 a) {
    __half2 lo = __floats2half2_rn(a.x, a.y);
    __half2 hi = __floats2half2_rn(a.z, a.w);
    uint2 r;
    r.x = *reinterpret_cast<unsigned*>(&lo);
    r.y = *reinterpret_cast<unsigned*>(&hi);
    return r;
}
// accumulate 8 fp16 dims (one uint4) scaled by al into two float4 accumulators
__device__ __forceinline__ void hfma8(float4& a0, float4& a1, uint4 u, float al) {
    __half2 h0 = *reinterpret_cast<__half2*>(&u.x);
    __half2 h1 = *reinterpret_cast<__half2*>(&u.y);
    __half2 h2 = *reinterpret_cast<__half2*>(&u.z);
    __half2 h3 = *reinterpret_cast<__half2*>(&u.w);
    float2 f0 = __half22float2(h0), f1 = __half22float2(h1);
    float2 f2 = __half22float2(h2), f3 = __half22float2(h3);
    a0.x += f0.x * al; a0.y += f0.y * al; a0.z += f1.x * al; a0.w += f1.y * al;
    a1.x += f2.x * al; a1.y += f2.y * al; a1.z += f3.x * al; a1.w += f3.y * al;
}

// ---------------- launch 0: degree count + initial linear -------------------
#define CNT_BLOCKS  CDIV(EE, 256)
#define LIN0_BLOCKS CDIV(NN * 16, 256)
__global__ __launch_bounds__(256) void k_count_lin0(const int* __restrict__ ei,
                                                    const float* __restrict__ x,
                                                    const float* __restrict__ lw,
                                                    const float* __restrict__ lb) {
    if (blockIdx.x < CNT_BLOCKS) {
        int i = blockIdx.x * 256 + threadIdx.x;
        if (i < EE) atomicAdd(&g_cursor[ei[EE + i]], 1);
    } else {
        int i = (blockIdx.x - CNT_BLOCKS) * 256 + threadIdx.x;
        if (i >= NN * 16) return;
        int n = i >> 4, c = i & 15;
        const float* xr = x + n * 10;
        const float* wr = lw + c * 10;
        float acc = lb[c];
        #pragma unroll
        for (int d = 0; d < 10; d++) acc += xr[d] * wr[d];
        reinterpret_cast<float*>(g_hin4)[i] = selu_f(acc);
    }
}

// ---------------- launch 1: scan, 4 elems/thread (adds self-loop +1) --------
__global__ void k_scan() {
    __shared__ int s_wtot[33];
    __shared__ int s_carry;
    int tid = threadIdx.x, lane = tid & 31, wid = tid >> 5;
    if (tid == 0) s_carry = 0;
    __syncthreads();
    const int4* cur4 = reinterpret_cast<const int4*>(g_cursor);
    int4* cw4 = reinterpret_cast<int4*>(g_cursor);
    int4* rp4 = reinterpret_cast<int4*>(g_rowptr);
    constexpr int N4 = NN / 4;       // 12500
    for (int base = 0; base < N4; base += 1024) {
        int i4 = base + tid;
        int4 v = {0, 0, 0, 0};
        if (i4 < N4) {
            v = cur4[i4];
            v.x++; v.y++; v.z++; v.w++;   // self loops
        }
        int t0 = v.x, t1 = t0 + v.y, t2 = t1 + v.z, t3 = t2 + v.w;
        int x = t3;
        #pragma unroll
        for (int o = 1; o < 32; o <<= 1) {
            int t = __shfl_up_sync(FULLM, x, o);
            if (lane >= o) x += t;
        }
        if (lane == 31) s_wtot[wid] = x;
        __syncthreads();
        if (wid == 0) {
            int w = s_wtot[lane];
            int y = w;
            #pragma unroll
            for (int o = 1; o < 32; o <<= 1) {
                int t = __shfl_up_sync(FULLM, y, o);
                if (lane >= o) y += t;
            }
            s_wtot[lane] = y - w;
            if (lane == 31) s_wtot[32] = y;
        }
        __syncthreads();
        int excl = s_carry + s_wtot[wid] + (x - t3);
        if (i4 < N4) {
            int4 r;
            r.x = excl; r.y = excl + t0; r.z = excl + t1; r.w = excl + t2;
            rp4[i4] = r;
            cw4[i4] = r;
        }
        int btot = s_wtot[32];
        __syncthreads();
        if (tid == 0) s_carry += btot;
        __syncthreads();
    }
    if (tid == 0) g_rowptr[NN] = s_carry;
}

// ---------------- transform / alpha device functions ------------------------
template <int DIN, int DOUT, int STRIDE>
__device__ __forceinline__ void dev_transform(float* s_buf, int blk,
                                              const float* __restrict__ W) {
    constexpr int HD = 6 * DOUT;
    constexpr int C4 = HD / 4;
    constexpr int C4S = STRIDE / 4;
    for (int i = threadIdx.x; i < DIN * HD; i += 256) {
        int k = i / DIN, d = i - k * DIN;
        s_buf[d * HD + k] = W[i];
    }
    __syncthreads();
    int t = blk * 256 + threadIdx.x;
    if (t >= (NN / 4) * C4S) return;
    int c4 = t % C4S, nb = t / C4S;
    int n0 = nb * 4;
    float4 acc0 = {0,0,0,0}, acc1 = {0,0,0,0}, acc2 = {0,0,0,0}, acc3 = {0,0,0,0};
    if (c4 < C4) {
        const float4* x4 = g_hin4;
        const float4* w4 = reinterpret_cast<const float4*>(s_buf);
        #pragma unroll
        for (int dc = 0; dc < DIN / 4; dc++) {
            float4 xv0 = x4[(n0 + 0) * (DIN / 4) + dc];
            float4 xv1 = x4[(n0 + 1) * (DIN / 4) + dc];
            float4 xv2 = x4[(n0 + 2) * (DIN / 4) + dc];
            float4 xv3 = x4[(n0 + 3) * (DIN / 4) + dc];
            #pragma unroll
            for (int j = 0; j < 4; j++) {
                float4 wv = w4[(dc * 4 + j) * C4 + c4];
                fma4(acc0, wv, f4c(xv0, j));
                fma4(acc1, wv, f4c(xv1, j));
                fma4(acc2, wv, f4c(xv2, j));
                fma4(acc3, wv, f4c(xv3, j));
            }
        }
    }
    __half* hb = g_hh;
    *reinterpret_cast<uint2*>(hb + (size_t)(n0 + 0) * STRIDE + c4 * 4) = f4_to_h4(acc0);
    *reinterpret_cast<uint2*>(hb + (size_t)(n0 + 1) * STRIDE + c4 * 4) = f4_to_h4(acc1);
    *reinterpret_cast<uint2*>(hb + (size_t)(n0 + 2) * STRIDE + c4 * 4) = f4_to_h4(acc2);
    *reinterpret_cast<uint2*>(hb + (size_t)(n0 + 3) * STRIDE + c4 * 4) = f4_to_h4(acc3);
}

template <int DIN, int DOUT>
__device__ __forceinline__ void dev_alpha(float* s_buf, int blk,
                                          const float* __restrict__ W,
                                          const float* __restrict__ asv,
                                          const float* __restrict__ adv) {
    for (int i = threadIdx.x; i < 12 * DIN; i += 256) {
        int d = i / 12, hh = i - d * 12;
        int head = hh % 6;
        const float* av = (hh < 6 ? asv : adv) + head * DOUT;
        float s = 0.f;
        #pragma unroll
        for (int o = 0; o < DOUT; o++) s += av[o] * W[(head * DOUT + o) * DIN + d];
        s_buf[d * 12 + hh] = s;
    }
    __syncthreads();
    int t2 = blk * 256 + threadIdx.x;
    if (t2 >= NN * 12) return;
    int n = t2 / 12, hh = t2 - n * 12;
    const float* xr = reinterpret_cast<const float*>(g_hin4) + n * DIN;
    float acc = 0.f;
    #pragma unroll
    for (int d = 0; d < DIN; d++) acc += xr[d] * s_buf[d * 12 + hh];
    reinterpret_cast<float*>(g_ae4)[n * 16 + (hh < 6 ? hh : hh + 2)] = acc;
}

// ---------------- launch 2: scatter + layer-1 feat (fused) ------------------
#define NBT1 CDIV((NN / 4) * 48, 256)
#define NBA  CDIV(NN * 12, 256)
#define SCAT_BLOCKS CDIV(ET, 256)
__global__ __launch_bounds__(256) void k_scatter_feat1(const int* __restrict__ ei,
                                                       const float* __restrict__ W,
                                                       const float* __restrict__ asv,
                                                       const float* __restrict__ adv) {
    __shared__ float s_buf[16 * 192];
    if (blockIdx.x < NBT1) {
        dev_transform<16, 32, 192>(s_buf, blockIdx.x, W);
    } else if (blockIdx.x < NBT1 + NBA) {
        dev_alpha<16, 32>(s_buf, blockIdx.x - NBT1, W, asv, adv);
    } else {
        int i = (blockIdx.x - NBT1 - NBA) * 256 + threadIdx.x;
        if (i >= ET) return;
        int s, d;
        if (i < EE) { s = ei[i]; d = ei[EE + i]; }
        else        { s = d = i - EE; }
        int pos = atomicAdd(&g_cursor[d], 1);
        g_csr[pos] = s;
    }
}

// ---------------- generic per-layer feat (layers 2-4) -----------------------
template <int DIN, int DOUT, int STRIDE, bool ZERO_CURSOR>
__global__ __launch_bounds__(256) void k_feat(const float* __restrict__ W,
                                              const float* __restrict__ asv,
                                              const float* __restrict__ adv) {
    __shared__ float s_buf[DIN * 6 * DOUT];
    constexpr int NBT = CDIV((NN / 4) * (STRIDE / 4), 256);
    if (blockIdx.x < NBT) {
        dev_transform<DIN, DOUT, STRIDE>(s_buf, blockIdx.x, W);
    } else if (blockIdx.x < NBT + NBA) {
        dev_alpha<DIN, DOUT>(s_buf, blockIdx.x - NBT, W, asv, adv);
    } else if (ZERO_CURSOR) {
        int i = (blockIdx.x - NBT - NBA) * 256 + threadIdx.x;
        if (i < NN) g_cursor[i] = 0;
    }
}

// ---------------- fused GAT -------------------------------------------------
template <int DOUT>
__global__ __launch_bounds__(256) void k_gat(const float* __restrict__ bias,
                                             float* __restrict__ out) {
    __shared__ float s_red[(DOUT > 2) ? 8 * 192 : 8];
    int w = threadIdx.x >> 5, lane = threadIdx.x & 31;
    int n = blockIdx.x * 8 + w;           // grid = NN/8 exactly
    int start = g_rowptr[n], end = g_rowptr[n + 1];
    int deg = end - start;

    const float4* ae4 = g_ae4;
    const float*  aef = reinterpret_cast<const float*>(g_ae4);
    float4 d03 = ae4[n * 4 + 2];
    float4 d45 = ae4[n * 4 + 3];
    float adh[6] = {d03.x, d03.y, d03.z, d03.w, d45.x, d45.y};
    float* sw = s_red + ((DOUT > 2) ? w * 192 : 0);
    const uint4* gh = reinterpret_cast<const uint4*>(g_hh);

    // ================= DOUT == 2 (HD=12, stride 16 halves) =================
    if constexpr (DOUT == 2) {
        float acc[12];
        #pragma unroll
        for (int k = 0; k < 12; k++) acc[k] = 0.f;
        if (deg <= 32) {
            int s = 0; bool act = lane < deg;
            if (act) s = g_csr[start + lane];
            float p[6], S[6];
            if (act) {
                float4 a03 = ae4[s * 4 + 0], a45 = ae4[s * 4 + 1];
                p[0] = __expf(lrelu(a03.x + adh[0]));
                p[1] = __expf(lrelu(a03.y + adh[1]));
                p[2] = __expf(lrelu(a03.z + adh[2]));
                p[3] = __expf(lrelu(a03.w + adh[3]));
                p[4] = __expf(lrelu(a45.x + adh[4]));
                p[5] = __expf(lrelu(a45.y + adh[5]));
            } else {
                #pragma unroll
                for (int h = 0; h < 6; h++) p[h] = 0.f;
            }
            #pragma unroll
            for (int h = 0; h < 6; h++) S[h] = p[h];
            #pragma unroll
            for (int h = 0; h < 6; h++)
                #pragma unroll
                for (int o = 16; o > 0; o >>= 1)
                    S[h] += __shfl_xor_sync(FULLM, S[h], o);
            float al[6];
            #pragma unroll
            for (int h = 0; h < 6; h++) al[h] = p[h] * (1.f / S[h]);
            if (act) {
                const uint4* hp = gh + s * 2;
                uint4 u0 = hp[0], u1 = hp[1];
                __half2* h0 = reinterpret_cast<__half2*>(&u0);
                __half2* h1 = reinterpret_cast<__half2*>(&u1);
                float2 f;
                f = __half22float2(h0[0]); acc[0] = f.x * al[0]; acc[1] = f.y * al[0];
                f = __half22float2(h0[1]); acc[2] = f.x * al[1]; acc[3] = f.y * al[1];
                f = __half22float2(h0[2]); acc[4] = f.x * al[2]; acc[5] = f.y * al[2];
                f = __half22float2(h0[3]); acc[6] = f.x * al[3]; acc[7] = f.y * al[3];
                f = __half22float2(h1[0]); acc[8] = f.x * al[4]; acc[9] = f.y * al[4];
                f = __half22float2(h1[1]); acc[10] = f.x * al[5]; acc[11] = f.y * al[5];
            }
        } else {
            // slow path
            float S[6];
            #pragma unroll
            for (int h = 0; h < 6; h++) S[h] = 0.f;
            for (int j = start + lane; j < end; j += 32) {
                int s = g_csr[j];
                float4 a03 = ae4[s * 4 + 0], a45 = ae4[s * 4 + 1];
                S[0] += __expf(lrelu(a03.x + adh[0]));
                S[1] += __expf(lrelu(a03.y + adh[1]));
                S[2] += __expf(lrelu(a03.z + adh[2]));
                S[3] += __expf(lrelu(a03.w + adh[3]));
                S[4] += __expf(lrelu(a45.x + adh[4]));
                S[5] += __expf(lrelu(a45.y + adh[5]));
            }
            #pragma unroll
            for (int h = 0; h < 6; h++)
                #pragma unroll
                for (int o = 16; o > 0; o >>= 1)
                    S[h] += __shfl_xor_sync(FULLM, S[h], o);
            float inv[6];
            #pragma unroll
            for (int h = 0; h < 6; h++) inv[h] = 1.f / S[h];
            for (int j = start + lane; j < end; j += 32) {
                int s = g_csr[j];
                float4 a03 = ae4[s * 4 + 0], a45 = ae4[s * 4 + 1];
                float al[6];
                al[0] = __expf(lrelu(a03.x + adh[0])) * inv[0];
                al[1] = __expf(lrelu(a03.y + adh[1])) * inv[1];
                al[2] = __expf(lrelu(a03.z + adh[2])) * inv[2];
                al[3] = __expf(lrelu(a03.w + adh[3])) * inv[3];
                al[4] = __expf(lrelu(a45.x + adh[4])) * inv[4];
                al[5] = __expf(lrelu(a45.y + adh[5])) * inv[5];
                const uint4* hp = gh + s * 2;
                uint4 u0 = hp[0], u1 = hp[1];
                __half2* h0 = reinterpret_cast<__half2*>(&u0);
                __half2* h1 = reinterpret_cast<__half2*>(&u1);
                float2 f;
                f = __half22float2(h0[0]); acc[0] += f.x * al[0]; acc[1] += f.y * al[0];
                f = __half22float2(h0[1]); acc[2] += f.x * al[1]; acc[3] += f.y * al[1];
                f = __half22float2(h0[2]); acc[4] += f.x * al[2]; acc[5] += f.y * al[2];
                f = __half22float2(h0[3]); acc[6] += f.x * al[3]; acc[7] += f.y * al[3];
                f = __half22float2(h1[0]); acc[8] += f.x * al[4]; acc[9] += f.y * al[4];
                f = __half22float2(h1[1]); acc[10] += f.x * al[5]; acc[11] += f.y * al[5];
            }
        }
        // head-sum per lane first, then reduce only 2 values (10 SHFL)
        float q0 = acc[0] + acc[2] + acc[4] + acc[6] + acc[8] + acc[10];
        float q1 = acc[1] + acc[3] + acc[5] + acc[7] + acc[9] + acc[11];
        #pragma unroll
        for (int o = 16; o > 0; o >>= 1) {
            q0 += __shfl_xor_sync(FULLM, q0, o);
            q1 += __shfl_xor_sync(FULLM, q1, o);
        }
        if (lane < 2) {
            float v = lane ? q1 : q0;
            out[n * 2 + lane] = selu_f(v * (1.f / 6.f) + bias[lane]);
        }
        return;
    }

    // ================= DOUT == 32 / 16 =================
    bool actl = lane < 24;
    int hidx, ll = 0, eo = 0;
    if constexpr (DOUT == 32) {
        hidx = actl ? (lane >> 2) : 0;
    } else {
        ll = actl ? (lane % 12) : 0;
        eo = actl ? (lane / 12) : 0;
        hidx = ll >> 1;
    }
    constexpr int NU4 = (DOUT == 32) ? 24 : 12;   // uint4 per node row
    float4 acc0 = {0,0,0,0}, acc1 = {0,0,0,0};

    if (deg <= 32) {
        // ---- fast path: lane-per-edge softmax (no max shift) ----
        int s = 0; bool act = lane < deg;
        if (act) s = g_csr[start + lane];
        float p[6], S[6];
        if (act) {
            float4 a03 = ae4[s * 4 + 0], a45 = ae4[s * 4 + 1];
            p[0] = __expf(lrelu(a03.x + adh[0]));
            p[1] = __expf(lrelu(a03.y + adh[1]));
            p[2] = __expf(lrelu(a03.z + adh[2]));
            p[3] = __expf(lrelu(a03.w + adh[3]));
            p[4] = __expf(lrelu(a45.x + adh[4]));
            p[5] = __expf(lrelu(a45.y + adh[5]));
        } else {
            #pragma unroll
            for (int h = 0; h < 6; h++) p[h] = 0.f;
        }
        #pragma unroll
        for (int h = 0; h < 6; h++) S[h] = p[h];
        #pragma unroll
        for (int h = 0; h < 6; h++)
            #pragma unroll
            for (int o = 16; o > 0; o >>= 1)
                S[h] += __shfl_xor_sync(FULLM, S[h], o);
        // stage alphas: sw[edge*6 + head]; inactive lanes stage zeros (padding)
        #pragma unroll
        for (int h = 0; h < 6; h++) sw[lane * 6 + h] = p[h] * (1.f / S[h]);
        __syncwarp();

        int degR = (deg + 3) & ~3;       // padded edges have alpha=0, s=0 (valid row)

        if constexpr (DOUT == 32) {
            for (int j = 0; j < degR; j += 4) {
                int s0 = __shfl_sync(FULLM, s, j);
                int s1 = __shfl_sync(FULLM, s, j + 1);
                int s2 = __shfl_sync(FULLM, s, j + 2);
                int s3 = __shfl_sync(FULLM, s, j + 3);
                float a0 = sw[(j + 0) * 6 + hidx];
                float a1 = sw[(j + 1) * 6 + hidx];
                float a2 = sw[(j + 2) * 6 + hidx];
                float a3 = sw[(j + 3) * 6 + hidx];
                uint4 v0 = {0,0,0,0}, v1 = {0,0,0,0}, v2 = {0,0,0,0}, v3 = {0,0,0,0};
                if (actl) {
                    v0 = gh[(size_t)s0 * NU4 + lane];
                    v1 = gh[(size_t)s1 * NU4 + lane];
                    v2 = gh[(size_t)s2 * NU4 + lane];
                    v3 = gh[(size_t)s3 * NU4 + lane];
                }
                hfma8(acc0, acc1, v0, a0);
                hfma8(acc0, acc1, v1, a1);
                hfma8(acc0, acc1, v2, a2);
                hfma8(acc0, acc1, v3, a3);
            }
        } else { // DOUT == 16: 4 edges per iter (2 per eo group)
            for (int j = 0; j < degR; j += 4) {
                int js0 = j + eo, js1 = j + 2 + eo;
                int t0 = __shfl_sync(FULLM, s, js0);
                int t1 = __shfl_sync(FULLM, s, js1);
                float a0 = actl ? sw[js0 * 6 + hidx] : 0.f;
                float a1 = actl ? sw[js1 * 6 + hidx] : 0.f;
                uint4 v0 = {0,0,0,0}, v1 = {0,0,0,0};
                if (actl) {
                    v0 = gh[(size_t)t0 * NU4 + ll];
                    v1 = gh[(size_t)t1 * NU4 + ll];
                }
                hfma8(acc0, acc1, v0, a0);
                hfma8(acc0, acc1, v1, a1);
            }
        }
    } else {
        // ---- slow path (deg > 32, rare) ----
        float S[6];
        #pragma unroll
        for (int h = 0; h < 6; h++) S[h] = 0.f;
        for (int j = start + lane; j < end; j += 32) {
            int s = g_csr[j];
            float4 a03 = ae4[s * 4 + 0], a45 = ae4[s * 4 + 1];
            S[0] += __expf(lrelu(a03.x + adh[0]));
            S[1] += __expf(lrelu(a03.y + adh[1]));
            S[2] += __expf(lrelu(a03.z + adh[2]));
            S[3] += __expf(lrelu(a03.w + adh[3]));
            S[4] += __expf(lrelu(a45.x + adh[4]));
            S[5] += __expf(lrelu(a45.y + adh[5]));
        }
        #pragma unroll
        for (int h = 0; h < 6; h++)
            #pragma unroll
            for (int o = 16; o > 0; o >>= 1)
                S[h] += __shfl_xor_sync(FULLM, S[h], o);
        float inv_sel = 0.f, ad_sel = 0.f;
        #pragma unroll
        for (int h = 0; h < 6; h++)
            if (hidx == h) { inv_sel = 1.f / S[h]; ad_sel = adh[h]; }

        bool act_agg = (DOUT == 32) ? actl : (actl && eo == 0);
        int dlane = (DOUT == 32) ? lane : ll;
        for (int j = start; j < end; j++) {
            int s0 = g_csr[j];
            float a = 0.f;
            uint4 v = {0,0,0,0};
            if (act_agg) {
                float e = lrelu(aef[s0 * 16 + hidx] + ad_sel);
                a = __expf(e) * inv_sel;
                v = gh[(size_t)s0 * NU4 + dlane];
            }
            hfma8(acc0, acc1, v, a);
        }
    }

    // ---- common epilogue: smem transpose, head mean + bias + SELU ----
    __syncwarp();
    if constexpr (DOUT == 32) {
        if (actl) {
            int b = lane * 8;
            sw[b + 0] = acc0.x; sw[b + 1] = acc0.y; sw[b + 2] = acc0.z; sw[b + 3] = acc0.w;
            sw[b + 4] = acc1.x; sw[b + 5] = acc1.y; sw[b + 6] = acc1.z; sw[b + 7] = acc1.w;
        }
        __syncwarp();
        float o0 = sw[lane] + sw[32 + lane] + sw[64 + lane] +
                   sw[96 + lane] + sw[128 + lane] + sw[160 + lane];
        out[n * 32 + lane] = selu_f(o0 * (1.f / 6.f) + bias[lane]);
    } else {
        if (actl) {
            int b = eo * 96 + ll * 8;
            sw[b + 0] = acc0.x; sw[b + 1] = acc0.y; sw[b + 2] = acc0.z; sw[b + 3] = acc0.w;
            sw[b + 4] = acc1.x; sw[b + 5] = acc1.y; sw[b + 6] = acc1.z; sw[b + 7] = acc1.w;
        }
        __syncwarp();
        if (lane < 16) {
            float o0 = 0.f;
            #pragma unroll
            for (int h = 0; h < 6; h++)
                o0 += sw[h * 16 + lane] + sw[96 + h * 16 + lane];
            out[n * 16 + lane] = selu_f(o0 * (1.f / 6.f) + bias[lane]);
        }
    }
}

// ---------------- host launcher ---------------------------------------------
extern "C" void kernel_launch(void* const* d_in, const int* in_sizes, int n_in,
                              void* d_out, int out_size) {
    (void)in_sizes; (void)n_in; (void)out_size;
    const float* x     = (const float*)d_in[0];
    const int*   ei    = (const int*)d_in[1];
    const float* lin_w = (const float*)d_in[2];
    const float* lin_b = (const float*)d_in[3];
    const float* W[4]  = { (const float*)d_in[4],  (const float*)d_in[8],
                           (const float*)d_in[12], (const float*)d_in[16] };
    const float* AS[4] = { (const float*)d_in[5],  (const float*)d_in[9],
                           (const float*)d_in[13], (const float*)d_in[17] };
    const float* AD[4] = { (const float*)d_in[6],  (const float*)d_in[10],
                           (const float*)d_in[14], (const float*)d_in[18] };
    const float* B[4]  = { (const float*)d_in[7],  (const float*)d_in[11],
                           (const float*)d_in[15], (const float*)d_in[19] };
    float* out = (float*)d_out;

    float* g_hin_ptr = nullptr;
    cudaGetSymbolAddress((void**)&g_hin_ptr, g_hin4);

    const int gat_blocks = NN / 8;

    // 0: count + lin0  (cursor zero: zero-init on first call, reset by feat4 after)
    k_count_lin0<<<CNT_BLOCKS + LIN0_BLOCKS, 256>>>(ei, x, lin_w, lin_b);
    // 1: scan
    k_scan<<<1, 1024>>>();
    // 2: scatter + layer-1 transform + alpha
    k_scatter_feat1<<<NBT1 + NBA + SCAT_BLOCKS, 256>>>(ei, W[0], AS[0], AD[0]);
    // 3: gat layer 1
    k_gat<32><<<gat_blocks, 256>>>(B[0], g_hin_ptr);
    // 4-5: layer 2   (launch 5 = gat32 L2 <- ncu capture target)
    k_feat<32, 32, 192, false><<<CDIV((NN / 4) * 48, 256) + NBA, 256>>>(W[1], AS[1], AD[1]);
    k_gat<32><<<gat_blocks, 256>>>(B[1], g_hin_ptr);
    // 6-7: layer 3
    k_feat<32, 16, 96, false><<<CDIV((NN / 4) * 24, 256) + NBA, 256>>>(W[2], AS[2], AD[2]);
    k_gat<16><<<gat_blocks, 256>>>(B[2], g_hin_ptr);
    // 8-9: layer 4 (+cursor re-zero for next call)
    k_feat<16, 2, 16, true><<<CDIV((NN / 4) * 4, 256) + NBA + CDIV(NN, 256), 256>>>(W[3], AS[3], AD[3]);
    k_gat<2><<<gat_blocks, 256>>>(B[3], out);
}